// round 11
// baseline (speedup 1.0000x reference)
#include <cuda_runtime.h>
#include <cuda_bf16.h>
#include <cuda_fp16.h>
#include <cstdint>
#include <cstddef>

#define N_NODES 100000
#define N_EDGES 3200000
#define NODE_F  256
#define EDGE_F  16
#define N_HEAD  8
#define OUT_F   256
#define N_TILES 1563   // ceil(100000/64)

// ---------------- scratch (static device globals; no allocation) ----------------
__device__ __align__(16) float g_fc[N_NODES * N_HEAD];
__device__ __align__(16) float g_as[N_NODES * N_HEAD];
__device__ __align__(16) float g_ad[N_NODES * N_HEAD];
__device__ __align__(16) __nv_bfloat16 g_eexp[(size_t)N_EDGES * N_HEAD];  // 51.2 MB packed
__device__ __align__(16) float g_sumd[N_NODES * N_HEAD];
__device__ __align__(16) float g_sums[N_NODES * N_HEAD];
__device__ __align__(16) float g_msg[N_NODES * N_HEAD];
__device__ __align__(16) float g_stats[2 * N_HEAD];
__device__ __align__(16) float g_w2[N_HEAD * OUT_F];
__device__ __align__(16) float g_b2[OUT_F];
// fp16-rounded features (single product scheme)
__device__ __align__(16) __half g_fh[(size_t)N_NODES * NODE_F];
// transposed weights: [n][k] = W[k][n], single fp16
__device__ __align__(16) __half g_WdT[256 * 256];
__device__ __align__(16) __half g_WaT[256 * 256];

// ---------------- helpers ----------------
__device__ __forceinline__ void red4(float* p, float a, float b, float c, float d) {
    asm volatile("red.global.add.v4.f32 [%0], {%1, %2, %3, %4};"
                 :: "l"(p), "f"(a), "f"(b), "f"(c), "f"(d) : "memory");
}
__device__ __forceinline__ float leaky(float x) { return x >= 0.f ? x : 0.2f * x; }

__device__ __forceinline__ uint32_t smem_u32(const void* p) {
    uint32_t a;
    asm("{ .reg .u64 t; cvta.to.shared.u64 t, %1; cvt.u32.u64 %0, t; }" : "=r"(a) : "l"(p));
    return a;
}
__device__ __forceinline__ uint32_t pack2h(float a, float b) {
    __half2 h = __floats2half2_rn(a, b);
    return *reinterpret_cast<uint32_t*>(&h);
}
__device__ __forceinline__ void ldsm4(uint32_t a, uint32_t r[4]) {
    asm volatile("ldmatrix.sync.aligned.m8n8.x4.shared.b16 {%0,%1,%2,%3}, [%4];"
                 : "=r"(r[0]), "=r"(r[1]), "=r"(r[2]), "=r"(r[3]) : "r"(a));
}
__device__ __forceinline__ void mma16816(float c[4], const uint32_t a[4], uint32_t b0, uint32_t b1) {
    asm volatile("mma.sync.aligned.m16n8k16.row.col.f32.f16.f16.f32 "
                 "{%0,%1,%2,%3}, {%4,%5,%6,%7}, {%8,%9}, {%0,%1,%2,%3};"
                 : "+f"(c[0]), "+f"(c[1]), "+f"(c[2]), "+f"(c[3])
                 : "r"(a[0]), "r"(a[1]), "r"(a[2]), "r"(a[3]), "r"(b0), "r"(b1));
}
__device__ __forceinline__ void cpa16(uint32_t dst, const void* src) {
    asm volatile("cp.async.cg.shared.global [%0], [%1], 16;" :: "r"(dst), "l"(src));
}
#define CP_COMMIT() asm volatile("cp.async.commit_group;" ::: "memory")
#define CP_WAIT(n)  asm volatile("cp.async.wait_group %0;" :: "n"(n) : "memory")

// ---------------- K1: node linear 256->24 + zero-init + fp16 feature round ----------------
__global__ __launch_bounds__(256) void k_node(const float* __restrict__ feat,
                                              const float* __restrict__ Wp,
                                              const float* __restrict__ Was,
                                              const float* __restrict__ Wad) {
    __shared__ float Ws[3 * 2048];     // [mat][h][k] : mat*2048 + h*256 + k
    __shared__ float fs[32 * 260];
    int tid = threadIdx.x;
    int row0 = blockIdx.x * 32;
    {
        int o = row0 * 8 + tid;
        g_sumd[o] = 0.f; g_sums[o] = 0.f; g_msg[o] = 0.f;
        if (blockIdx.x == 0 && tid < 16) g_stats[tid] = 0.f;
    }
    for (int i = tid; i < 2048; i += 256) {
        int k = i >> 3, h = i & 7;
        Ws[h * 256 + k]        = Wp[i];
        Ws[2048 + h * 256 + k] = Was[i];
        Ws[4096 + h * 256 + k] = Wad[i];
    }
    for (int i = tid; i < 32 * 256; i += 256) {
        int r = i >> 8, c = i & 255;
        fs[r * 260 + c] = feat[(size_t)(row0 + r) * 256 + c];
    }
    __syncthreads();
    // fp16 round of features (single-product GEMM A)
    for (int i = tid; i < 32 * 128; i += 256) {
        int r = i >> 7, c2 = (i & 127) * 2;
        uint32_t hi = pack2h(fs[r * 260 + c2], fs[r * 260 + c2 + 1]);
        ((uint32_t*)g_fh)[((size_t)(row0 + r) * 256 + c2) >> 1] = hi;
    }
    int r = tid >> 3, h = tid & 7;
    const float4* f4 = (const float4*)(fs + r * 260);
    const float4* w0 = (const float4*)(Ws + h * 256);
    const float4* w1 = (const float4*)(Ws + 2048 + h * 256);
    const float4* w2 = (const float4*)(Ws + 4096 + h * 256);
    float a0 = 0.f, a1 = 0.f, a2 = 0.f;
#pragma unroll 8
    for (int k4 = 0; k4 < 64; k4++) {
        float4 f = f4[k4];
        float4 p = w0[k4], q = w1[k4], w = w2[k4];
        a0 += f.x * p.x + f.y * p.y + f.z * p.z + f.w * p.w;
        a1 += f.x * q.x + f.y * q.y + f.z * q.z + f.w * q.w;
        a2 += f.x * w.x + f.y * w.y + f.z * w.z + f.w * w.w;
    }
    int n = row0 + r;
    g_fc[n * 8 + h] = a0;
    g_as[n * 8 + h] = a1;
    g_ad[n * 8 + h] = a2;
}

// ---------------- K1b: transpose + fp16-round weights ----------------
__global__ void k_split(const float* __restrict__ Wd, const float* __restrict__ Wa) {
    __shared__ float t[32][33];
    const float* W = blockIdx.z ? Wa : Wd;
    __half* O = blockIdx.z ? g_WaT : g_WdT;
    int kb = blockIdx.x * 32, nb = blockIdx.y * 32;
    int tx = threadIdx.x;
    for (int ty = threadIdx.y; ty < 32; ty += 8)
        t[ty][tx] = W[(size_t)(kb + ty) * 256 + nb + tx];
    __syncthreads();
    for (int ty = threadIdx.y; ty < 32; ty += 8)
        O[(size_t)(nb + ty) * 256 + kb + tx] = __float2half_rn(t[tx][ty]);
}

// ---------------- K2: edge attention, exp, scatter sums ----------------
__global__ __launch_bounds__(256) void k_edge1(const float* __restrict__ fe,
                                               const int* __restrict__ src,
                                               const int* __restrict__ dst,
                                               const float* __restrict__ Wae) {
    __shared__ float4 Wv[32];
    int tid = threadIdx.x;
    if (tid < 32) Wv[tid] = ((const float4*)Wae)[tid];
    __syncthreads();
    int e = blockIdx.x * 256 + tid;
    if (e >= N_EDGES) return;
    int s = src[e], d = dst[e];

    const float4* fp = (const float4*)(fe + (size_t)e * 16);
    float4 f0 = fp[0], f1 = fp[1], f2 = fp[2], f3 = fp[3];

    float v[8];
    {
        const float4* ap = (const float4*)(g_as + (size_t)s * 8);
        const float4* bp = (const float4*)(g_ad + (size_t)d * 8);
        float4 a0 = ap[0], a1 = ap[1], b0 = bp[0], b1 = bp[1];
        v[0] = a0.x + b0.x; v[1] = a0.y + b0.y; v[2] = a0.z + b0.z; v[3] = a0.w + b0.w;
        v[4] = a1.x + b1.x; v[5] = a1.y + b1.y; v[6] = a1.z + b1.z; v[7] = a1.w + b1.w;
    }
#define ADDK(F, K) { float4 wa = Wv[2*(K)], wb = Wv[2*(K)+1]; \
    v[0] += (F)*wa.x; v[1] += (F)*wa.y; v[2] += (F)*wa.z; v[3] += (F)*wa.w; \
    v[4] += (F)*wb.x; v[5] += (F)*wb.y; v[6] += (F)*wb.z; v[7] += (F)*wb.w; }
    ADDK(f0.x, 0)  ADDK(f0.y, 1)  ADDK(f0.z, 2)  ADDK(f0.w, 3)
    ADDK(f1.x, 4)  ADDK(f1.y, 5)  ADDK(f1.z, 6)  ADDK(f1.w, 7)
    ADDK(f2.x, 8)  ADDK(f2.y, 9)  ADDK(f2.z, 10) ADDK(f2.w, 11)
    ADDK(f3.x, 12) ADDK(f3.y, 13) ADDK(f3.z, 14) ADDK(f3.w, 15)
#undef ADDK

    float ex[8];
#pragma unroll
    for (int h = 0; h < 8; h++) ex[h] = __expf(leaky(v[h]));

    __nv_bfloat162 p[4];
    p[0] = __floats2bfloat162_rn(ex[0], ex[1]);
    p[1] = __floats2bfloat162_rn(ex[2], ex[3]);
    p[2] = __floats2bfloat162_rn(ex[4], ex[5]);
    p[3] = __floats2bfloat162_rn(ex[6], ex[7]);
    *(uint4*)(g_eexp + (size_t)e * 8) = *reinterpret_cast<uint4*>(p);

    red4(g_sumd + (size_t)d * 8,     ex[0], ex[1], ex[2], ex[3]);
    red4(g_sumd + (size_t)d * 8 + 4, ex[4], ex[5], ex[6], ex[7]);
    red4(g_sums + (size_t)s * 8,     ex[0], ex[1], ex[2], ex[3]);
    red4(g_sums + (size_t)s * 8 + 4, ex[4], ex[5], ex[6], ex[7]);
}

// ---------------- K2b: per-node strength reduction (in-place) ----------------
__global__ __launch_bounds__(256) void k_rs() {
    int i = blockIdx.x * 256 + threadIdx.x;
    if (i < N_NODES * N_HEAD) {
        g_sumd[i] = rsqrtf(g_sumd[i]);
        g_fc[i] *= rsqrtf(g_sums[i]);
    }
}

// ---------------- K3: dual-softmax coeff + message scatter ----------------
__global__ __launch_bounds__(256) void k_edge2(const int* __restrict__ src,
                                               const int* __restrict__ dst) {
    int e = blockIdx.x * 256 + threadIdx.x;
    if (e >= N_EDGES) return;
    int s = src[e], d = dst[e];
    uint4 raw = *(const uint4*)(g_eexp + (size_t)e * 8);
    const __nv_bfloat162* pr = reinterpret_cast<const __nv_bfloat162*>(&raw);
    float2 e01 = __bfloat1622float2(pr[0]);
    float2 e23 = __bfloat1622float2(pr[1]);
    float2 e45 = __bfloat1622float2(pr[2]);
    float2 e67 = __bfloat1622float2(pr[3]);
    const float4* sdp = (const float4*)(g_sumd + (size_t)d * 8);   // rsqrt(sumd)
    const float4* fcp = (const float4*)(g_fc   + (size_t)s * 8);   // fc * rsqrt(sums)
    float4 sd0 = sdp[0], sd1 = sdp[1];
    float4 c0 = fcp[0], c1 = fcp[1];

    float m0 = e01.x * sd0.x * c0.x;
    float m1 = e01.y * sd0.y * c0.y;
    float m2 = e23.x * sd0.z * c0.z;
    float m3 = e23.y * sd0.w * c0.w;
    float m4 = e45.x * sd1.x * c1.x;
    float m5 = e45.y * sd1.y * c1.y;
    float m6 = e67.x * sd1.z * c1.z;
    float m7 = e67.y * sd1.w * c1.w;

    red4(g_msg + (size_t)d * 8,     m0, m1, m2, m3);
    red4(g_msg + (size_t)d * 8 + 4, m4, m5, m6, m7);
}

// ---------------- K4: BN statistics ----------------
__global__ __launch_bounds__(256) void k_stats() {
    int n = blockIdx.x * 256 + threadIdx.x;
    float a[8], q[8];
#pragma unroll
    for (int h = 0; h < 8; h++) { a[h] = 0.f; q[h] = 0.f; }
    if (n < N_NODES) {
        const float4* mp = (const float4*)(g_msg + (size_t)n * 8);
        float4 m0 = mp[0], m1 = mp[1];
        a[0] = m0.x; a[1] = m0.y; a[2] = m0.z; a[3] = m0.w;
        a[4] = m1.x; a[5] = m1.y; a[6] = m1.z; a[7] = m1.w;
#pragma unroll
        for (int h = 0; h < 8; h++) q[h] = a[h] * a[h];
    }
#pragma unroll
    for (int h = 0; h < 8; h++) {
        for (int off = 16; off; off >>= 1) {
            a[h] += __shfl_xor_sync(0xFFFFFFFFu, a[h], off);
            q[h] += __shfl_xor_sync(0xFFFFFFFFu, q[h], off);
        }
    }
    if ((threadIdx.x & 31) == 0) {
#pragma unroll
        for (int h = 0; h < 8; h++) {
            atomicAdd(&g_stats[h], a[h]);
            atomicAdd(&g_stats[8 + h], q[h]);
        }
    }
}

// ---------------- K5: fold BN + W_agg + b_apply_dst into W2 / b2 ----------------
__global__ void k_prep(const float* __restrict__ gamma, const float* __restrict__ beta,
                       const float* __restrict__ Wagg, const float* __restrict__ bagg,
                       const float* __restrict__ bapd) {
    __shared__ float sc[8], sh[8];
    int tid = threadIdx.x;
    if (tid < 8) {
        float mu  = g_stats[tid] * (1.f / N_NODES);
        float var = g_stats[8 + tid] * (1.f / N_NODES) - mu * mu;
        float s = gamma[tid] * rsqrtf(var + 1e-5f);
        sc[tid] = s;
        sh[tid] = beta[tid] - mu * s;
    }
    __syncthreads();
    int c = tid;
    float b = bagg[c] + bapd[c];
#pragma unroll
    for (int h = 0; h < 8; h++) {
        float w = Wagg[h * 256 + c];
        g_w2[h * 256 + c] = sc[h] * w;
        b += sh[h] * w;
    }
    g_b2[c] = b;
}

// ---------------- K6: fused double GEMM, single-fp16 operands, 64-row CTA, 2 CTAs/SM ----
// smem (bytes):
#define IH    0         // A1 chunk (stride 144) / inter fp16 (stride 528, 33792) / epi2 stage part
#define BO    33792     // B single buffer 256*144 = 36864
#define W2O   70656     // w2 8*256*4 = 8192
#define MSO   78848     // msgs 64*8*4 = 2048
#define TC_SMEM 80896   // 2 CTAs/SM with slack

__device__ __forceinline__ void gemm_chunk(float acc[2][8][4],
                                           uint32_t aB, uint32_t astride,
                                           uint32_t bB, int wm, int wn, int lane) {
    const uint32_t arow = (uint32_t)(wm * 32 + (lane & 15));
    const uint32_t akh  = (uint32_t)((lane >> 4) * 8);
    const uint32_t brow = (uint32_t)(wn * 64 + (lane & 7) + ((lane >> 4) & 1) * 8);
    const uint32_t bkh  = (uint32_t)(((lane >> 3) & 1) * 8);
#pragma unroll
    for (int ks = 0; ks < 64; ks += 16) {
        uint32_t a[2][4];
#pragma unroll
        for (int mi = 0; mi < 2; mi++) {
            uint32_t ao = (arow + mi * 16) * astride + (ks + akh) * 2;
            ldsm4(aB + ao, a[mi]);
        }
#pragma unroll
        for (int nip = 0; nip < 4; nip++) {
            uint32_t bo = (brow + nip * 16) * 144 + (ks + bkh) * 2;
            uint32_t b[4];
            ldsm4(bB + bo, b);
#pragma unroll
            for (int mi = 0; mi < 2; mi++) {
                mma16816(acc[mi][nip * 2],     a[mi], b[0], b[1]);
                mma16816(acc[mi][nip * 2 + 1], a[mi], b[2], b[3]);
            }
        }
    }
}

__global__ void __launch_bounds__(256, 2) k_tc(const float* __restrict__ bap,
                                               float* __restrict__ out) {
    extern __shared__ char sm[];
    const uint32_t sb = smem_u32(sm);
    const int tid = threadIdx.x;
    const int warp = tid >> 5, lane = tid & 31;
    const int wm = warp >> 2, wn = warp & 3;
    const int row0 = blockIdx.x * 64;

    float* w2s  = (float*)(sm + W2O);
    float* msgs = (float*)(sm + MSO);

    auto pfA = [&](int kc) {
#pragma unroll
        for (int i = tid; i < 512; i += 256) {
            int r = i >> 3, s = i & 7;
            int node = row0 + r; if (node >= N_NODES) node = N_NODES - 1;
            cpa16(sb + IH + (uint32_t)(r * 144 + s * 16),
                  g_fh + (size_t)node * 256 + kc + s * 8);
        }
    };
    auto pfB = [&](const __half* W, int kc) {
#pragma unroll
        for (int i = tid; i < 2048; i += 256) {
            int n = i >> 3, s = i & 7;
            cpa16(sb + BO + (uint32_t)(n * 144 + s * 16), W + (size_t)n * 256 + kc + s * 8);
        }
    };

    for (int i = tid; i < 2048; i += 256) w2s[i] = g_w2[i];
    for (int i = tid; i < 512; i += 256) {
        int r = i >> 3;
        int node = row0 + r; if (node >= N_NODES) node = N_NODES - 1;
        msgs[i] = g_msg[(size_t)node * 8 + (i & 7)];
    }

    float acc[2][8][4];
#pragma unroll
    for (int mi = 0; mi < 2; mi++)
#pragma unroll
        for (int ni = 0; ni < 8; ni++)
#pragma unroll
            for (int j = 0; j < 4; j++) acc[mi][ni][j] = 0.f;

    // ================= GEMM1: feat(fp16) @ WdT =================
#pragma unroll
    for (int ci = 0; ci < 4; ci++) {
        pfA(ci * 64);
        pfB(g_WdT, ci * 64);
        CP_COMMIT();
        CP_WAIT(0);
        __syncthreads();
        gemm_chunk(acc, sb + IH, 144, sb + BO, wm, wn, lane);
        __syncthreads();
    }

    // ====== epilogue1: + bias + msg@W2, leaky, fp16 round -> inter (stride 528B) ======
    {
        const int g = lane >> 2, t = lane & 3;
#pragma unroll
        for (int mi = 0; mi < 2; mi++) {
            const int rA = wm * 32 + mi * 16 + g, rB = rA + 8;
            float mA[8], mB[8];
#pragma unroll
            for (int h = 0; h < 8; h++) { mA[h] = msgs[rA * 8 + h]; mB[h] = msgs[rB * 8 + h]; }
#pragma unroll
            for (int ni = 0; ni < 8; ni++) {
                const int c0 = wn * 64 + ni * 8 + 2 * t, c1 = c0 + 1;
                float b0 = g_b2[c0], b1 = g_b2[c1];
                float vA0 = acc[mi][ni][0] + b0;
                float vA1 = acc[mi][ni][1] + b1;
                float vB0 = acc[mi][ni][2] + b0;
                float vB1 = acc[mi][ni][3] + b1;
#pragma unroll
                for (int h = 0; h < 8; h++) {
                    float w0 = w2s[h * 256 + c0], w1 = w2s[h * 256 + c1];
                    vA0 += mA[h] * w0; vA1 += mA[h] * w1;
                    vB0 += mB[h] * w0; vB1 += mB[h] * w1;
                }
                *(uint32_t*)(sm + IH + rA * 528 + c0 * 2) = pack2h(leaky(vA0), leaky(vA1));
                *(uint32_t*)(sm + IH + rB * 528 + c0 * 2) = pack2h(leaky(vB0), leaky(vB1));
                acc[mi][ni][0] = 0.f; acc[mi][ni][1] = 0.f;
                acc[mi][ni][2] = 0.f; acc[mi][ni][3] = 0.f;
            }
        }
    }

    // ================= GEMM2: inter(fp16) @ WaT =================
#pragma unroll
    for (int ci = 0; ci < 4; ci++) {
        pfB(g_WaT, ci * 64);
        CP_COMMIT();
        CP_WAIT(0);
        __syncthreads();
        gemm_chunk(acc, sb + IH + ci * 128, 528, sb + BO, wm, wn, lane);
        __syncthreads();
    }

    // ====== epilogue2: + ba -> stage (fp32, stride 264 floats) -> coalesced store ======
    {
        float* stage = (float*)(sm + IH);   // 64*264*4 = 67584, spans IH+BO
        const int g = lane >> 2, t = lane & 3;
#pragma unroll
        for (int mi = 0; mi < 2; mi++) {
            const int rA = wm * 32 + mi * 16 + g, rB = rA + 8;
#pragma unroll
            for (int ni = 0; ni < 8; ni++) {
                const int c0 = wn * 64 + ni * 8 + 2 * t;
                float b0 = bap[c0], b1 = bap[c0 + 1];
                *(float2*)(stage + rA * 264 + c0) = make_float2(acc[mi][ni][0] + b0, acc[mi][ni][1] + b1);
                *(float2*)(stage + rB * 264 + c0) = make_float2(acc[mi][ni][2] + b0, acc[mi][ni][3] + b1);
            }
        }
        __syncthreads();
        for (int idx = tid; idx < 64 * 64; idx += 256) {
            int r = idx >> 6, c4 = (idx & 63) << 2;
            int node = row0 + r;
            if (node < N_NODES)
                *(float4*)(out + (size_t)node * 256 + c4) = *(const float4*)(stage + r * 264 + c4);
        }
    }
}

// ---------------- launch ----------------
extern "C" void kernel_launch(void* const* d_in, const int* in_sizes, int n_in,
                              void* d_out, int out_size) {
    const float* feat  = (const float*)d_in[0];
    const float* fedge = (const float*)d_in[1];
    const int*   src   = (const int*)d_in[2];
    const int*   dst   = (const int*)d_in[3];
    const float* Wp    = (const float*)d_in[4];
    const float* Was   = (const float*)d_in[5];
    const float* Wad   = (const float*)d_in[6];
    const float* Wae   = (const float*)d_in[7];
    const float* gamma = (const float*)d_in[8];
    const float* beta  = (const float*)d_in[9];
    const float* Wagg  = (const float*)d_in[10];
    const float* bagg  = (const float*)d_in[11];
    const float* Wapd  = (const float*)d_in[12];
    const float* bapd  = (const float*)d_in[13];
    const float* Wap   = (const float*)d_in[14];
    const float* bap   = (const float*)d_in[15];
    float* out = (float*)d_out;

    k_node<<<N_NODES / 32, 256>>>(feat, Wp, Was, Wad);
    k_split<<<dim3(8, 8, 2), dim3(32, 8)>>>(Wapd, Wap);
    k_edge1<<<(N_EDGES + 255) / 256, 256>>>(fedge, src, dst, Wae);
    k_rs<<<(N_NODES * N_HEAD + 255) / 256, 256>>>();
    k_edge2<<<(N_EDGES + 255) / 256, 256>>>(src, dst);
    k_stats<<<(N_NODES + 255) / 256, 256>>>();
    k_prep<<<1, 256>>>(gamma, beta, Wagg, bagg, bapd);

    cudaFuncSetAttribute(k_tc, cudaFuncAttributeMaxDynamicSharedMemorySize, TC_SMEM);
    k_tc<<<N_TILES, 256, TC_SMEM>>>(bap, out);
}

// round 12
// speedup vs baseline: 1.3149x; 1.3149x over previous
#include <cuda_runtime.h>
#include <cuda_bf16.h>
#include <cuda_fp16.h>
#include <cstdint>
#include <cstddef>

#define N_NODES 100000
#define N_EDGES 3200000
#define NODE_F  256
#define EDGE_F  16
#define N_HEAD  8
#define OUT_F   256
#define N_TILES 1563   // ceil(100000/64)

// ---------------- scratch (static device globals; no allocation) ----------------
__device__ __align__(16) float g_fc[N_NODES * N_HEAD];
__device__ __align__(16) float g_as[N_NODES * N_HEAD];
__device__ __align__(16) float g_ad[N_NODES * N_HEAD];
__device__ __align__(16) __nv_bfloat16 g_eexp[(size_t)N_EDGES * N_HEAD];  // 51.2 MB packed
__device__ __align__(16) float g_sumd[N_NODES * N_HEAD];
__device__ __align__(16) float g_sums[N_NODES * N_HEAD];
__device__ __align__(16) float g_msg[N_NODES * N_HEAD];
__device__ __align__(16) float g_stats[2 * N_HEAD];
__device__ __align__(16) float g_w2[N_HEAD * OUT_F];
__device__ __align__(16) float g_b2[OUT_F];
// fp16-rounded features (single-product scheme)
__device__ __align__(16) __half g_fh[(size_t)N_NODES * NODE_F];
// transposed weights: [n][k] = W[k][n], single fp16
__device__ __align__(16) __half g_WdT[256 * 256];
__device__ __align__(16) __half g_WaT[256 * 256];

// ---------------- helpers ----------------
__device__ __forceinline__ void red4(float* p, float a, float b, float c, float d) {
    asm volatile("red.global.add.v4.f32 [%0], {%1, %2, %3, %4};"
                 :: "l"(p), "f"(a), "f"(b), "f"(c), "f"(d) : "memory");
}
__device__ __forceinline__ float leaky(float x) { return x >= 0.f ? x : 0.2f * x; }

__device__ __forceinline__ uint32_t smem_u32(const void* p) {
    uint32_t a;
    asm("{ .reg .u64 t; cvta.to.shared.u64 t, %1; cvt.u32.u64 %0, t; }" : "=r"(a) : "l"(p));
    return a;
}
__device__ __forceinline__ uint32_t pack2h(float a, float b) {
    __half2 h = __floats2half2_rn(a, b);
    return *reinterpret_cast<uint32_t*>(&h);
}
__device__ __forceinline__ void ldsm4(uint32_t a, uint32_t r[4]) {
    asm volatile("ldmatrix.sync.aligned.m8n8.x4.shared.b16 {%0,%1,%2,%3}, [%4];"
                 : "=r"(r[0]), "=r"(r[1]), "=r"(r[2]), "=r"(r[3]) : "r"(a));
}
__device__ __forceinline__ void mma16816(float c[4], const uint32_t a[4], uint32_t b0, uint32_t b1) {
    asm volatile("mma.sync.aligned.m16n8k16.row.col.f32.f16.f16.f32 "
                 "{%0,%1,%2,%3}, {%4,%5,%6,%7}, {%8,%9}, {%0,%1,%2,%3};"
                 : "+f"(c[0]), "+f"(c[1]), "+f"(c[2]), "+f"(c[3])
                 : "r"(a[0]), "r"(a[1]), "r"(a[2]), "r"(a[3]), "r"(b0), "r"(b1));
}
__device__ __forceinline__ void cpa16(uint32_t dst, const void* src) {
    asm volatile("cp.async.cg.shared.global [%0], [%1], 16;" :: "r"(dst), "l"(src));
}
#define CP_COMMIT() asm volatile("cp.async.commit_group;" ::: "memory")
#define CP_WAIT(n)  asm volatile("cp.async.wait_group %0;" :: "n"(n) : "memory")

// ---------------- K1: node linear 256->24 + zero-init + fp16 feature round ----------------
// (R9 structure: conflict-free Ws[k*24+h] layout; split loop now stores single fp16)
__global__ __launch_bounds__(256) void k_node(const float* __restrict__ feat,
                                              const float* __restrict__ Wp,
                                              const float* __restrict__ Was,
                                              const float* __restrict__ Wad) {
    __shared__ float Ws[256 * 24];
    __shared__ float fs[32 * 260];
    int tid = threadIdx.x;
    int row0 = blockIdx.x * 32;
    {
        int o = row0 * 8 + tid;
        g_sumd[o] = 0.f; g_sums[o] = 0.f; g_msg[o] = 0.f;
        if (blockIdx.x == 0 && tid < 16) g_stats[tid] = 0.f;
    }
    for (int i = tid; i < 256 * 8; i += 256) {
        int k = i >> 3, h = i & 7;
        Ws[k * 24 + h]      = Wp[i];
        Ws[k * 24 + 8 + h]  = Was[i];
        Ws[k * 24 + 16 + h] = Wad[i];
    }
    for (int i = tid; i < 32 * 256; i += 256) {
        int r = i >> 8, c = i & 255;
        fs[r * 260 + c] = feat[(size_t)(row0 + r) * 256 + c];
    }
    __syncthreads();
    // fp16 round of features (single-product GEMM A operand)
    for (int i = tid; i < 32 * 128; i += 256) {
        int r = i >> 7, c2 = (i & 127) * 2;
        ((uint32_t*)g_fh)[((size_t)(row0 + r) * 256 + c2) >> 1] =
            pack2h(fs[r * 260 + c2], fs[r * 260 + c2 + 1]);
    }
    int r = tid >> 3, h = tid & 7;
    const float* fr = fs + r * 260;
    float a0 = 0.f, a1 = 0.f, a2 = 0.f;
#pragma unroll 8
    for (int k = 0; k < 256; k++) {
        float f = fr[k];
        a0 += f * Ws[k * 24 + h];
        a1 += f * Ws[k * 24 + 8 + h];
        a2 += f * Ws[k * 24 + 16 + h];
    }
    int n = row0 + r;
    g_fc[n * 8 + h] = a0;
    g_as[n * 8 + h] = a1;
    g_ad[n * 8 + h] = a2;
}

// ---------------- K1b: transpose + fp16-round weights ----------------
__global__ void k_split(const float* __restrict__ Wd, const float* __restrict__ Wa) {
    __shared__ float t[32][33];
    const float* W = blockIdx.z ? Wa : Wd;
    __half* O = blockIdx.z ? g_WaT : g_WdT;
    int kb = blockIdx.x * 32, nb = blockIdx.y * 32;
    int tx = threadIdx.x;
    for (int ty = threadIdx.y; ty < 32; ty += 8)
        t[ty][tx] = W[(size_t)(kb + ty) * 256 + nb + tx];
    __syncthreads();
    for (int ty = threadIdx.y; ty < 32; ty += 8)
        O[(size_t)(nb + ty) * 256 + kb + tx] = __float2half_rn(t[tx][ty]);
}

// ---------------- K2: edge attention, exp, scatter sums ----------------
__global__ __launch_bounds__(256) void k_edge1(const float* __restrict__ fe,
                                               const int* __restrict__ src,
                                               const int* __restrict__ dst,
                                               const float* __restrict__ Wae) {
    __shared__ float4 Wv[32];
    int tid = threadIdx.x;
    if (tid < 32) Wv[tid] = ((const float4*)Wae)[tid];
    __syncthreads();
    int e = blockIdx.x * 256 + tid;
    if (e >= N_EDGES) return;
    int s = src[e], d = dst[e];

    const float4* fp = (const float4*)(fe + (size_t)e * 16);
    float4 f0 = fp[0], f1 = fp[1], f2 = fp[2], f3 = fp[3];

    float v[8];
    {
        const float4* ap = (const float4*)(g_as + (size_t)s * 8);
        const float4* bp = (const float4*)(g_ad + (size_t)d * 8);
        float4 a0 = ap[0], a1 = ap[1], b0 = bp[0], b1 = bp[1];
        v[0] = a0.x + b0.x; v[1] = a0.y + b0.y; v[2] = a0.z + b0.z; v[3] = a0.w + b0.w;
        v[4] = a1.x + b1.x; v[5] = a1.y + b1.y; v[6] = a1.z + b1.z; v[7] = a1.w + b1.w;
    }
#define ADDK(F, K) { float4 wa = Wv[2*(K)], wb = Wv[2*(K)+1]; \
    v[0] += (F)*wa.x; v[1] += (F)*wa.y; v[2] += (F)*wa.z; v[3] += (F)*wa.w; \
    v[4] += (F)*wb.x; v[5] += (F)*wb.y; v[6] += (F)*wb.z; v[7] += (F)*wb.w; }
    ADDK(f0.x, 0)  ADDK(f0.y, 1)  ADDK(f0.z, 2)  ADDK(f0.w, 3)
    ADDK(f1.x, 4)  ADDK(f1.y, 5)  ADDK(f1.z, 6)  ADDK(f1.w, 7)
    ADDK(f2.x, 8)  ADDK(f2.y, 9)  ADDK(f2.z, 10) ADDK(f2.w, 11)
    ADDK(f3.x, 12) ADDK(f3.y, 13) ADDK(f3.z, 14) ADDK(f3.w, 15)
#undef ADDK

    float ex[8];
#pragma unroll
    for (int h = 0; h < 8; h++) ex[h] = __expf(leaky(v[h]));

    __nv_bfloat162 p[4];
    p[0] = __floats2bfloat162_rn(ex[0], ex[1]);
    p[1] = __floats2bfloat162_rn(ex[2], ex[3]);
    p[2] = __floats2bfloat162_rn(ex[4], ex[5]);
    p[3] = __floats2bfloat162_rn(ex[6], ex[7]);
    *(uint4*)(g_eexp + (size_t)e * 8) = *reinterpret_cast<uint4*>(p);

    red4(g_sumd + (size_t)d * 8,     ex[0], ex[1], ex[2], ex[3]);
    red4(g_sumd + (size_t)d * 8 + 4, ex[4], ex[5], ex[6], ex[7]);
    red4(g_sums + (size_t)s * 8,     ex[0], ex[1], ex[2], ex[3]);
    red4(g_sums + (size_t)s * 8 + 4, ex[4], ex[5], ex[6], ex[7]);
}

// ---------------- K2b: per-node strength reduction (in-place) ----------------
__global__ __launch_bounds__(256) void k_rs() {
    int i = blockIdx.x * 256 + threadIdx.x;
    if (i < N_NODES * N_HEAD) {
        g_sumd[i] = rsqrtf(g_sumd[i]);
        g_fc[i] *= rsqrtf(g_sums[i]);
    }
}

// ---------------- K3: dual-softmax coeff + message scatter ----------------
__global__ __launch_bounds__(256) void k_edge2(const int* __restrict__ src,
                                               const int* __restrict__ dst) {
    int e = blockIdx.x * 256 + threadIdx.x;
    if (e >= N_EDGES) return;
    int s = src[e], d = dst[e];
    uint4 raw = *(const uint4*)(g_eexp + (size_t)e * 8);
    const __nv_bfloat162* pr = reinterpret_cast<const __nv_bfloat162*>(&raw);
    float2 e01 = __bfloat1622float2(pr[0]);
    float2 e23 = __bfloat1622float2(pr[1]);
    float2 e45 = __bfloat1622float2(pr[2]);
    float2 e67 = __bfloat1622float2(pr[3]);
    const float4* sdp = (const float4*)(g_sumd + (size_t)d * 8);   // rsqrt(sumd)
    const float4* fcp = (const float4*)(g_fc   + (size_t)s * 8);   // fc * rsqrt(sums)
    float4 sd0 = sdp[0], sd1 = sdp[1];
    float4 c0 = fcp[0], c1 = fcp[1];

    float m0 = e01.x * sd0.x * c0.x;
    float m1 = e01.y * sd0.y * c0.y;
    float m2 = e23.x * sd0.z * c0.z;
    float m3 = e23.y * sd0.w * c0.w;
    float m4 = e45.x * sd1.x * c1.x;
    float m5 = e45.y * sd1.y * c1.y;
    float m6 = e67.x * sd1.z * c1.z;
    float m7 = e67.y * sd1.w * c1.w;

    red4(g_msg + (size_t)d * 8,     m0, m1, m2, m3);
    red4(g_msg + (size_t)d * 8 + 4, m4, m5, m6, m7);
}

// ---------------- K4: BN statistics ----------------
__global__ __launch_bounds__(256) void k_stats() {
    int n = blockIdx.x * 256 + threadIdx.x;
    float a[8], q[8];
#pragma unroll
    for (int h = 0; h < 8; h++) { a[h] = 0.f; q[h] = 0.f; }
    if (n < N_NODES) {
        const float4* mp = (const float4*)(g_msg + (size_t)n * 8);
        float4 m0 = mp[0], m1 = mp[1];
        a[0] = m0.x; a[1] = m0.y; a[2] = m0.z; a[3] = m0.w;
        a[4] = m1.x; a[5] = m1.y; a[6] = m1.z; a[7] = m1.w;
#pragma unroll
        for (int h = 0; h < 8; h++) q[h] = a[h] * a[h];
    }
#pragma unroll
    for (int h = 0; h < 8; h++) {
        for (int off = 16; off; off >>= 1) {
            a[h] += __shfl_xor_sync(0xFFFFFFFFu, a[h], off);
            q[h] += __shfl_xor_sync(0xFFFFFFFFu, q[h], off);
        }
    }
    if ((threadIdx.x & 31) == 0) {
#pragma unroll
        for (int h = 0; h < 8; h++) {
            atomicAdd(&g_stats[h], a[h]);
            atomicAdd(&g_stats[8 + h], q[h]);
        }
    }
}

// ---------------- K5: fold BN + W_agg + b_apply_dst into W2 / b2 ----------------
__global__ void k_prep(const float* __restrict__ gamma, const float* __restrict__ beta,
                       const float* __restrict__ Wagg, const float* __restrict__ bagg,
                       const float* __restrict__ bapd) {
    __shared__ float sc[8], sh[8];
    int tid = threadIdx.x;
    if (tid < 8) {
        float mu  = g_stats[tid] * (1.f / N_NODES);
        float var = g_stats[8 + tid] * (1.f / N_NODES) - mu * mu;
        float s = gamma[tid] * rsqrtf(var + 1e-5f);
        sc[tid] = s;
        sh[tid] = beta[tid] - mu * s;
    }
    __syncthreads();
    int c = tid;
    float b = bagg[c] + bapd[c];
#pragma unroll
    for (int h = 0; h < 8; h++) {
        float w = Wagg[h * 256 + c];
        g_w2[h * 256 + c] = sc[h] * w;
        b += sh[h] * w;
    }
    g_b2[c] = b;
}

// ---------------- K6: fused double GEMM, single-fp16 operands, 64-row CTA, 2 CTAs/SM ----
#define IH    0         // A1 chunk (stride 144) / inter fp16 (stride 528, 33792) / epi2 stage part
#define BO    33792     // B single buffer 256*144 = 36864
#define W2O   70656     // w2 8*256*4 = 8192
#define MSO   78848     // msgs 64*8*4 = 2048
#define TC_SMEM 80896   // 2 CTAs/SM

__device__ __forceinline__ void gemm_chunk(float acc[2][8][4],
                                           uint32_t aB, uint32_t astride,
                                           uint32_t bB, int wm, int wn, int lane) {
    const uint32_t arow = (uint32_t)(wm * 32 + (lane & 15));
    const uint32_t akh  = (uint32_t)((lane >> 4) * 8);
    const uint32_t brow = (uint32_t)(wn * 64 + (lane & 7) + ((lane >> 4) & 1) * 8);
    const uint32_t bkh  = (uint32_t)(((lane >> 3) & 1) * 8);
#pragma unroll
    for (int ks = 0; ks < 64; ks += 16) {
        uint32_t a[2][4];
#pragma unroll
        for (int mi = 0; mi < 2; mi++) {
            uint32_t ao = (arow + mi * 16) * astride + (ks + akh) * 2;
            ldsm4(aB + ao, a[mi]);
        }
#pragma unroll
        for (int nip = 0; nip < 4; nip++) {
            uint32_t bo = (brow + nip * 16) * 144 + (ks + bkh) * 2;
            uint32_t b[4];
            ldsm4(bB + bo, b);
#pragma unroll
            for (int mi = 0; mi < 2; mi++) {
                mma16816(acc[mi][nip * 2],     a[mi], b[0], b[1]);
                mma16816(acc[mi][nip * 2 + 1], a[mi], b[2], b[3]);
            }
        }
    }
}

__global__ void __launch_bounds__(256, 2) k_tc(const float* __restrict__ bap,
                                               float* __restrict__ out) {
    extern __shared__ char sm[];
    const uint32_t sb = smem_u32(sm);
    const int tid = threadIdx.x;
    const int warp = tid >> 5, lane = tid & 31;
    const int wm = warp >> 2, wn = warp & 3;
    const int row0 = blockIdx.x * 64;

    float* w2s  = (float*)(sm + W2O);
    float* msgs = (float*)(sm + MSO);

    auto pfA = [&](int kc) {
#pragma unroll
        for (int i = tid; i < 512; i += 256) {
            int r = i >> 3, s = i & 7;
            int node = row0 + r; if (node >= N_NODES) node = N_NODES - 1;
            cpa16(sb + IH + (uint32_t)(r * 144 + s * 16),
                  g_fh + (size_t)node * 256 + kc + s * 8);
        }
    };
    auto pfB = [&](const __half* W, int kc) {
#pragma unroll
        for (int i = tid; i < 2048; i += 256) {
            int n = i >> 3, s = i & 7;
            cpa16(sb + BO + (uint32_t)(n * 144 + s * 16), W + (size_t)n * 256 + kc + s * 8);
        }
    };

    for (int i = tid; i < 2048; i += 256) w2s[i] = g_w2[i];
    for (int i = tid; i < 512; i += 256) {
        int r = i >> 3;
        int node = row0 + r; if (node >= N_NODES) node = N_NODES - 1;
        msgs[i] = g_msg[(size_t)node * 8 + (i & 7)];
    }

    float acc[2][8][4];
#pragma unroll
    for (int mi = 0; mi < 2; mi++)
#pragma unroll
        for (int ni = 0; ni < 8; ni++)
#pragma unroll
            for (int j = 0; j < 4; j++) acc[mi][ni][j] = 0.f;

    // ================= GEMM1: feat(fp16) @ WdT =================
#pragma unroll
    for (int ci = 0; ci < 4; ci++) {
        pfA(ci * 64);
        pfB(g_WdT, ci * 64);
        CP_COMMIT();
        CP_WAIT(0);
        __syncthreads();
        gemm_chunk(acc, sb + IH, 144, sb + BO, wm, wn, lane);
        __syncthreads();
    }

    // ====== epilogue1: + bias + msg@W2, leaky, fp16 round -> inter (stride 528B) ======
    {
        const int g = lane >> 2, t = lane & 3;
#pragma unroll
        for (int mi = 0; mi < 2; mi++) {
            const int rA = wm * 32 + mi * 16 + g, rB = rA + 8;
            float mA[8], mB[8];
#pragma unroll
            for (int h = 0; h < 8; h++) { mA[h] = msgs[rA * 8 + h]; mB[h] = msgs[rB * 8 + h]; }
#pragma unroll
            for (int ni = 0; ni < 8; ni++) {
                const int c0 = wn * 64 + ni * 8 + 2 * t, c1 = c0 + 1;
                float b0 = g_b2[c0], b1 = g_b2[c1];
                float vA0 = acc[mi][ni][0] + b0;
                float vA1 = acc[mi][ni][1] + b1;
                float vB0 = acc[mi][ni][2] + b0;
                float vB1 = acc[mi][ni][3] + b1;
#pragma unroll
                for (int h = 0; h < 8; h++) {
                    float w0 = w2s[h * 256 + c0], w1 = w2s[h * 256 + c1];
                    vA0 += mA[h] * w0; vA1 += mA[h] * w1;
                    vB0 += mB[h] * w0; vB1 += mB[h] * w1;
                }
                *(uint32_t*)(sm + IH + rA * 528 + c0 * 2) = pack2h(leaky(vA0), leaky(vA1));
                *(uint32_t*)(sm + IH + rB * 528 + c0 * 2) = pack2h(leaky(vB0), leaky(vB1));
                acc[mi][ni][0] = 0.f; acc[mi][ni][1] = 0.f;
                acc[mi][ni][2] = 0.f; acc[mi][ni][3] = 0.f;
            }
        }
    }

    // ================= GEMM2: inter(fp16) @ WaT =================
#pragma unroll
    for (int ci = 0; ci < 4; ci++) {
        pfB(g_WaT, ci * 64);
        CP_COMMIT();
        CP_WAIT(0);
        __syncthreads();
        gemm_chunk(acc, sb + IH + ci * 128, 528, sb + BO, wm, wn, lane);
        __syncthreads();
    }

    // ====== epilogue2: + ba -> stage (fp32, stride 264 floats) -> coalesced store ======
    {
        float* stage = (float*)(sm + IH);   // 64*264*4 = 67584, spans IH+BO (both dead now)
        const int g = lane >> 2, t = lane & 3;
#pragma unroll
        for (int mi = 0; mi < 2; mi++) {
            const int rA = wm * 32 + mi * 16 + g, rB = rA + 8;
#pragma unroll
            for (int ni = 0; ni < 8; ni++) {
                const int c0 = wn * 64 + ni * 8 + 2 * t;
                float b0 = bap[c0], b1 = bap[c0 + 1];
                *(float2*)(stage + rA * 264 + c0) = make_float2(acc[mi][ni][0] + b0, acc[mi][ni][1] + b1);
                *(float2*)(stage + rB * 264 + c0) = make_float2(acc[mi][ni][2] + b0, acc[mi][ni][3] + b1);
            }
        }
        __syncthreads();
        for (int idx = tid; idx < 64 * 64; idx += 256) {
            int r = idx >> 6, c4 = (idx & 63) << 2;
            int node = row0 + r;
            if (node < N_NODES)
                *(float4*)(out + (size_t)node * 256 + c4) = *(const float4*)(stage + r * 264 + c4);
        }
    }
}

// ---------------- launch ----------------
extern "C" void kernel_launch(void* const* d_in, const int* in_sizes, int n_in,
                              void* d_out, int out_size) {
    const float* feat  = (const float*)d_in[0];
    const float* fedge = (const float*)d_in[1];
    const int*   src   = (const int*)d_in[2];
    const int*   dst   = (const int*)d_in[3];
    const float* Wp    = (const float*)d_in[4];
    const float* Was   = (const float*)d_in[5];
    const float* Wad   = (const float*)d_in[6];
    const float* Wae   = (const float*)d_in[7];
    const float* gamma = (const float*)d_in[8];
    const float* beta  = (const float*)d_in[9];
    const float* Wagg  = (const float*)d_in[10];
    const float* bagg  = (const float*)d_in[11];
    const float* Wapd  = (const float*)d_in[12];
    const float* bapd  = (const float*)d_in[13];
    const float* Wap   = (const float*)d_in[14];
    const float* bap   = (const float*)d_in[15];
    float* out = (float*)d_out;

    k_node<<<N_NODES / 32, 256>>>(feat, Wp, Was, Wad);
    k_split<<<dim3(8, 8, 2), dim3(32, 8)>>>(Wapd, Wap);
    k_edge1<<<(N_EDGES + 255) / 256, 256>>>(fedge, src, dst, Wae);
    k_rs<<<(N_NODES * N_HEAD + 255) / 256, 256>>>();
    k_edge2<<<(N_EDGES + 255) / 256, 256>>>(src, dst);
    k_stats<<<(N_NODES + 255) / 256, 256>>>();
    k_prep<<<1, 256>>>(gamma, beta, Wagg, bagg, bapd);

    cudaFuncSetAttribute(k_tc, cudaFuncAttributeMaxDynamicSharedMemorySize, TC_SMEM);
    k_tc<<<N_TILES, 256, TC_SMEM>>>(bap, out);
}

// round 13
// speedup vs baseline: 1.7144x; 1.3039x over previous
#include <cuda_runtime.h>
#include <cuda_bf16.h>
#include <cuda_fp16.h>
#include <cstdint>
#include <cstddef>

#define N_NODES 100000
#define N_EDGES 3200000
#define NODE_F  256
#define EDGE_F  16
#define N_HEAD  8
#define OUT_F   256
#define N_TILES 1563   // ceil(100000/64)

// ---------------- scratch (static device globals; no allocation) ----------------
__device__ __align__(16) float g_fc[N_NODES * N_HEAD];
__device__ __align__(16) float g_as[N_NODES * N_HEAD];
__device__ __align__(16) float g_ad[N_NODES * N_HEAD];
__device__ __align__(16) __nv_bfloat16 g_eexp[(size_t)N_EDGES * N_HEAD];  // 51.2 MB packed
__device__ __align__(16) float g_sumd[N_NODES * N_HEAD];
__device__ __align__(16) float g_sums[N_NODES * N_HEAD];
__device__ __align__(16) float g_msg[N_NODES * N_HEAD];
__device__ __align__(16) float g_stats[2 * N_HEAD];
__device__ __align__(16) float g_w2[N_HEAD * OUT_F];
__device__ __align__(16) float g_b2[OUT_F];
// pre-split features: fp16 hi/lo (feat = hi + lo to ~2^-22)
__device__ __align__(16) __half g_fh[(size_t)N_NODES * NODE_F];
__device__ __align__(16) __half g_fl[(size_t)N_NODES * NODE_F];
// transposed weights: [n][k] = W[k][n], single fp16
__device__ __align__(16) __half g_WdT[256 * 256];
__device__ __align__(16) __half g_WaT[256 * 256];

// ---------------- helpers ----------------
__device__ __forceinline__ void red4(float* p, float a, float b, float c, float d) {
    asm volatile("red.global.add.v4.f32 [%0], {%1, %2, %3, %4};"
                 :: "l"(p), "f"(a), "f"(b), "f"(c), "f"(d) : "memory");
}
__device__ __forceinline__ float leaky(float x) { return x >= 0.f ? x : 0.2f * x; }

__device__ __forceinline__ uint32_t smem_u32(const void* p) {
    uint32_t a;
    asm("{ .reg .u64 t; cvta.to.shared.u64 t, %1; cvt.u32.u64 %0, t; }" : "=r"(a) : "l"(p));
    return a;
}
__device__ __forceinline__ void split2h(float a, float b, uint32_t& hi, uint32_t& lo) {
    __half2 h = __floats2half2_rn(a, b);
    float2 hf = __half22float2(h);
    __half2 l = __floats2half2_rn(a - hf.x, b - hf.y);
    hi = *reinterpret_cast<uint32_t*>(&h);
    lo = *reinterpret_cast<uint32_t*>(&l);
}
__device__ __forceinline__ void ldsm4(uint32_t a, uint32_t r[4]) {
    asm volatile("ldmatrix.sync.aligned.m8n8.x4.shared.b16 {%0,%1,%2,%3}, [%4];"
                 : "=r"(r[0]), "=r"(r[1]), "=r"(r[2]), "=r"(r[3]) : "r"(a));
}
__device__ __forceinline__ void mma16816(float c[4], const uint32_t a[4], uint32_t b0, uint32_t b1) {
    asm volatile("mma.sync.aligned.m16n8k16.row.col.f32.f16.f16.f32 "
                 "{%0,%1,%2,%3}, {%4,%5,%6,%7}, {%8,%9}, {%0,%1,%2,%3};"
                 : "+f"(c[0]), "+f"(c[1]), "+f"(c[2]), "+f"(c[3])
                 : "r"(a[0]), "r"(a[1]), "r"(a[2]), "r"(a[3]), "r"(b0), "r"(b1));
}
__device__ __forceinline__ void cpa16(uint32_t dst, const void* src) {
    asm volatile("cp.async.cg.shared.global [%0], [%1], 16;" :: "r"(dst), "l"(src));
}
#define CP_COMMIT() asm volatile("cp.async.commit_group;" ::: "memory")
#define CP_WAIT(n)  asm volatile("cp.async.wait_group %0;" :: "n"(n) : "memory")

// ---------------- K1: node linear 256->24 + zero-init + feature split ----------------
__global__ __launch_bounds__(256) void k_node(const float* __restrict__ feat,
                                              const float* __restrict__ Wp,
                                              const float* __restrict__ Was,
                                              const float* __restrict__ Wad) {
    __shared__ float Ws[256 * 24];
    __shared__ float fs[32 * 260];
    int tid = threadIdx.x;
    int row0 = blockIdx.x * 32;
    {
        int o = row0 * 8 + tid;
        g_sumd[o] = 0.f; g_sums[o] = 0.f; g_msg[o] = 0.f;
        if (blockIdx.x == 0 && tid < 16) g_stats[tid] = 0.f;
    }
    for (int i = tid; i < 256 * 8; i += 256) {
        int k = i >> 3, h = i & 7;
        Ws[k * 24 + h]      = Wp[i];
        Ws[k * 24 + 8 + h]  = Was[i];
        Ws[k * 24 + 16 + h] = Wad[i];
    }
    for (int i = tid; i < 32 * 256; i += 256) {
        int r = i >> 8, c = i & 255;
        fs[r * 260 + c] = feat[(size_t)(row0 + r) * 256 + c];
    }
    __syncthreads();
    // feature split: 32 rows x 256 cols -> fp16 hi/lo (half2 stores)
    for (int i = tid; i < 32 * 128; i += 256) {
        int r = i >> 7, c2 = (i & 127) * 2;
        float a = fs[r * 260 + c2], b = fs[r * 260 + c2 + 1];
        uint32_t hi, lo;
        split2h(a, b, hi, lo);
        size_t o = ((size_t)(row0 + r) * 256 + c2) >> 1;
        ((uint32_t*)g_fh)[o] = hi;
        ((uint32_t*)g_fl)[o] = lo;
    }
    int r = tid >> 3, h = tid & 7;
    const float* fr = fs + r * 260;
    float a0 = 0.f, a1 = 0.f, a2 = 0.f;
#pragma unroll 8
    for (int k = 0; k < 256; k++) {
        float f = fr[k];
        a0 += f * Ws[k * 24 + h];
        a1 += f * Ws[k * 24 + 8 + h];
        a2 += f * Ws[k * 24 + 16 + h];
    }
    int n = row0 + r;
    g_fc[n * 8 + h] = a0;
    g_as[n * 8 + h] = a1;
    g_ad[n * 8 + h] = a2;
}

// ---------------- K1b: transpose + fp16-round weights ----------------
__global__ void k_split(const float* __restrict__ Wd, const float* __restrict__ Wa) {
    __shared__ float t[32][33];
    const float* W = blockIdx.z ? Wa : Wd;
    __half* O = blockIdx.z ? g_WaT : g_WdT;
    int kb = blockIdx.x * 32, nb = blockIdx.y * 32;
    int tx = threadIdx.x;
    for (int ty = threadIdx.y; ty < 32; ty += 8)
        t[ty][tx] = W[(size_t)(kb + ty) * 256 + nb + tx];
    __syncthreads();
    for (int ty = threadIdx.y; ty < 32; ty += 8)
        O[(size_t)(nb + ty) * 256 + kb + tx] = __float2half_rn(t[tx][ty]);
}

// ---------------- K2: edge attention, exp, scatter sums ----------------
__global__ __launch_bounds__(256) void k_edge1(const float* __restrict__ fe,
                                               const int* __restrict__ src,
                                               const int* __restrict__ dst,
                                               const float* __restrict__ Wae) {
    __shared__ float4 Wv[32];
    int tid = threadIdx.x;
    if (tid < 32) Wv[tid] = ((const float4*)Wae)[tid];
    __syncthreads();
    int e = blockIdx.x * 256 + tid;
    if (e >= N_EDGES) return;
    int s = src[e], d = dst[e];

    const float4* fp = (const float4*)(fe + (size_t)e * 16);
    float4 f0 = fp[0], f1 = fp[1], f2 = fp[2], f3 = fp[3];

    float v[8];
    {
        const float4* ap = (const float4*)(g_as + (size_t)s * 8);
        const float4* bp = (const float4*)(g_ad + (size_t)d * 8);
        float4 a0 = ap[0], a1 = ap[1], b0 = bp[0], b1 = bp[1];
        v[0] = a0.x + b0.x; v[1] = a0.y + b0.y; v[2] = a0.z + b0.z; v[3] = a0.w + b0.w;
        v[4] = a1.x + b1.x; v[5] = a1.y + b1.y; v[6] = a1.z + b1.z; v[7] = a1.w + b1.w;
    }
#define ADDK(F, K) { float4 wa = Wv[2*(K)], wb = Wv[2*(K)+1]; \
    v[0] += (F)*wa.x; v[1] += (F)*wa.y; v[2] += (F)*wa.z; v[3] += (F)*wa.w; \
    v[4] += (F)*wb.x; v[5] += (F)*wb.y; v[6] += (F)*wb.z; v[7] += (F)*wb.w; }
    ADDK(f0.x, 0)  ADDK(f0.y, 1)  ADDK(f0.z, 2)  ADDK(f0.w, 3)
    ADDK(f1.x, 4)  ADDK(f1.y, 5)  ADDK(f1.z, 6)  ADDK(f1.w, 7)
    ADDK(f2.x, 8)  ADDK(f2.y, 9)  ADDK(f2.z, 10) ADDK(f2.w, 11)
    ADDK(f3.x, 12) ADDK(f3.y, 13) ADDK(f3.z, 14) ADDK(f3.w, 15)
#undef ADDK

    float ex[8];
#pragma unroll
    for (int h = 0; h < 8; h++) ex[h] = __expf(leaky(v[h]));

    __nv_bfloat162 p[4];
    p[0] = __floats2bfloat162_rn(ex[0], ex[1]);
    p[1] = __floats2bfloat162_rn(ex[2], ex[3]);
    p[2] = __floats2bfloat162_rn(ex[4], ex[5]);
    p[3] = __floats2bfloat162_rn(ex[6], ex[7]);
    *(uint4*)(g_eexp + (size_t)e * 8) = *reinterpret_cast<uint4*>(p);

    red4(g_sumd + (size_t)d * 8,     ex[0], ex[1], ex[2], ex[3]);
    red4(g_sumd + (size_t)d * 8 + 4, ex[4], ex[5], ex[6], ex[7]);
    red4(g_sums + (size_t)s * 8,     ex[0], ex[1], ex[2], ex[3]);
    red4(g_sums + (size_t)s * 8 + 4, ex[4], ex[5], ex[6], ex[7]);
}

// ---------------- K2b: per-node strength reduction (in-place) ----------------
__global__ __launch_bounds__(256) void k_rs() {
    int i = blockIdx.x * 256 + threadIdx.x;
    if (i < N_NODES * N_HEAD) {
        g_sumd[i] = rsqrtf(g_sumd[i]);
        g_fc[i] *= rsqrtf(g_sums[i]);
    }
}

// ---------------- K3: dual-softmax coeff + message scatter ----------------
__global__ __launch_bounds__(256) void k_edge2(const int* __restrict__ src,
                                               const int* __restrict__ dst) {
    int e = blockIdx.x * 256 + threadIdx.x;
    if (e >= N_EDGES) return;
    int s = src[e], d = dst[e];
    uint4 raw = *(const uint4*)(g_eexp + (size_t)e * 8);
    const __nv_bfloat162* pr = reinterpret_cast<const __nv_bfloat162*>(&raw);
    float2 e01 = __bfloat1622float2(pr[0]);
    float2 e23 = __bfloat1622float2(pr[1]);
    float2 e45 = __bfloat1622float2(pr[2]);
    float2 e67 = __bfloat1622float2(pr[3]);
    const float4* sdp = (const float4*)(g_sumd + (size_t)d * 8);   // rsqrt(sumd)
    const float4* fcp = (const float4*)(g_fc   + (size_t)s * 8);   // fc * rsqrt(sums)
    float4 sd0 = sdp[0], sd1 = sdp[1];
    float4 c0 = fcp[0], c1 = fcp[1];

    float m0 = e01.x * sd0.x * c0.x;
    float m1 = e01.y * sd0.y * c0.y;
    float m2 = e23.x * sd0.z * c0.z;
    float m3 = e23.y * sd0.w * c0.w;
    float m4 = e45.x * sd1.x * c1.x;
    float m5 = e45.y * sd1.y * c1.y;
    float m6 = e67.x * sd1.z * c1.z;
    float m7 = e67.y * sd1.w * c1.w;

    red4(g_msg + (size_t)d * 8,     m0, m1, m2, m3);
    red4(g_msg + (size_t)d * 8 + 4, m4, m5, m6, m7);
}

// ---------------- K4: BN statistics ----------------
__global__ __launch_bounds__(256) void k_stats() {
    int n = blockIdx.x * 256 + threadIdx.x;
    float a[8], q[8];
#pragma unroll
    for (int h = 0; h < 8; h++) { a[h] = 0.f; q[h] = 0.f; }
    if (n < N_NODES) {
        const float4* mp = (const float4*)(g_msg + (size_t)n * 8);
        float4 m0 = mp[0], m1 = mp[1];
        a[0] = m0.x; a[1] = m0.y; a[2] = m0.z; a[3] = m0.w;
        a[4] = m1.x; a[5] = m1.y; a[6] = m1.z; a[7] = m1.w;
#pragma unroll
        for (int h = 0; h < 8; h++) q[h] = a[h] * a[h];
    }
#pragma unroll
    for (int h = 0; h < 8; h++) {
        for (int off = 16; off; off >>= 1) {
            a[h] += __shfl_xor_sync(0xFFFFFFFFu, a[h], off);
            q[h] += __shfl_xor_sync(0xFFFFFFFFu, q[h], off);
        }
    }
    if ((threadIdx.x & 31) == 0) {
#pragma unroll
        for (int h = 0; h < 8; h++) {
            atomicAdd(&g_stats[h], a[h]);
            atomicAdd(&g_stats[8 + h], q[h]);
        }
    }
}

// ---------------- K5: fold BN + W_agg + b_apply_dst into W2 / b2 ----------------
__global__ void k_prep(const float* __restrict__ gamma, const float* __restrict__ beta,
                       const float* __restrict__ Wagg, const float* __restrict__ bagg,
                       const float* __restrict__ bapd) {
    __shared__ float sc[8], sh[8];
    int tid = threadIdx.x;
    if (tid < 8) {
        float mu  = g_stats[tid] * (1.f / N_NODES);
        float var = g_stats[8 + tid] * (1.f / N_NODES) - mu * mu;
        float s = gamma[tid] * rsqrtf(var + 1e-5f);
        sc[tid] = s;
        sh[tid] = beta[tid] - mu * s;
    }
    __syncthreads();
    int c = tid;
    float b = bagg[c] + bapd[c];
#pragma unroll
    for (int h = 0; h < 8; h++) {
        float w = Wagg[h * 256 + c];
        g_w2[h * 256 + c] = sc[h] * w;
        b += sh[h] * w;
    }
    g_b2[c] = b;
}

// ---------------- K6: fused double GEMM, 64-row CTA, 2 CTAs/SM ----------------
#define IH    0
#define IL    33792     // inter_lo mirror / GEMM1 Alo
#define BO    67584     // B single buffer 256*144 = 36864
#define W2O   104448    // w2 8*256*4 = 8192
#define MSO   112640    // msgs 64*8*4 = 2048
#define TC_SMEM 114688  // 2 CTAs/SM

__device__ __forceinline__ void gemm_chunk(float acc[2][8][4],
                                           uint32_t ahB, uint32_t alB, uint32_t astride,
                                           uint32_t bB, int wm, int wn, int lane) {
    const uint32_t arow = (uint32_t)(wm * 32 + (lane & 15));
    const uint32_t akh  = (uint32_t)((lane >> 4) * 8);
    const uint32_t brow = (uint32_t)(wn * 64 + (lane & 7) + ((lane >> 4) & 1) * 8);
    const uint32_t bkh  = (uint32_t)(((lane >> 3) & 1) * 8);
#pragma unroll
    for (int ks = 0; ks < 64; ks += 16) {
        uint32_t ah[2][4], al[2][4];
#pragma unroll
        for (int mi = 0; mi < 2; mi++) {
            uint32_t ao = (arow + mi * 16) * astride + (ks + akh) * 2;
            ldsm4(ahB + ao, ah[mi]);
            ldsm4(alB + ao, al[mi]);
        }
#pragma unroll
        for (int nip = 0; nip < 4; nip++) {
            uint32_t bo = (brow + nip * 16) * 144 + (ks + bkh) * 2;
            uint32_t b[4];
            ldsm4(bB + bo, b);
#pragma unroll
            for (int mi = 0; mi < 2; mi++) {
                mma16816(acc[mi][nip * 2],     ah[mi], b[0], b[1]);
                mma16816(acc[mi][nip * 2],     al[mi], b[0], b[1]);
                mma16816(acc[mi][nip * 2 + 1], ah[mi], b[2], b[3]);
                mma16816(acc[mi][nip * 2 + 1], al[mi], b[2], b[3]);
            }
        }
    }
}

__global__ void __launch_bounds__(256, 2) k_tc(const float* __restrict__ bap,
                                               float* __restrict__ out) {
    extern __shared__ char sm[];
    const uint32_t sb = smem_u32(sm);
    const int tid = threadIdx.x;
    const int warp = tid >> 5, lane = tid & 31;
    const int wm = warp >> 2, wn = warp & 3;
    const int row0 = blockIdx.x * 64;

    float* w2s  = (float*)(sm + W2O);
    float* msgs = (float*)(sm + MSO);

    auto pfA = [&](int kc) {
#pragma unroll
        for (int i = tid; i < 512; i += 256) {
            int r = i >> 3, s = i & 7;
            int node = row0 + r; if (node >= N_NODES) node = N_NODES - 1;
            size_t off = (size_t)node * 256 + kc + s * 8;
            uint32_t d = (uint32_t)(r * 144 + s * 16);
            cpa16(sb + IH + d, g_fh + off);
            cpa16(sb + IL + d, g_fl + off);
        }
    };
    auto pfB = [&](const __half* W, int kc) {
#pragma unroll
        for (int i = tid; i < 2048; i += 256) {
            int n = i >> 3, s = i & 7;
            cpa16(sb + BO + (uint32_t)(n * 144 + s * 16), W + (size_t)n * 256 + kc + s * 8);
        }
    };

    for (int i = tid; i < 2048; i += 256) w2s[i] = g_w2[i];
    for (int i = tid; i < 512; i += 256) {
        int r = i >> 3;
        int node = row0 + r; if (node >= N_NODES) node = N_NODES - 1;
        msgs[i] = g_msg[(size_t)node * 8 + (i & 7)];
    }

    float acc[2][8][4];
#pragma unroll
    for (int mi = 0; mi < 2; mi++)
#pragma unroll
        for (int ni = 0; ni < 8; ni++)
#pragma unroll
            for (int j = 0; j < 4; j++) acc[mi][ni][j] = 0.f;

    // ================= GEMM1: feat @ Wd =================
#pragma unroll
    for (int ci = 0; ci < 4; ci++) {
        pfA(ci * 64);
        pfB(g_WdT, ci * 64);
        CP_COMMIT();
        CP_WAIT(0);
        __syncthreads();
        gemm_chunk(acc, sb + IH, sb + IL, 144, sb + BO, wm, wn, lane);
        __syncthreads();
    }

    // ====== epilogue1: + bias + msg@W2, leaky, re-split -> inter (stride 528B) ======
    {
        const int g = lane >> 2, t = lane & 3;
#pragma unroll
        for (int mi = 0; mi < 2; mi++) {
            const int rA = wm * 32 + mi * 16 + g, rB = rA + 8;
            float mA[8], mB[8];
#pragma unroll
            for (int h = 0; h < 8; h++) { mA[h] = msgs[rA * 8 + h]; mB[h] = msgs[rB * 8 + h]; }
#pragma unroll
            for (int ni = 0; ni < 8; ni++) {
                const int c0 = wn * 64 + ni * 8 + 2 * t, c1 = c0 + 1;
                float b0 = g_b2[c0], b1 = g_b2[c1];
                float vA0 = acc[mi][ni][0] + b0;
                float vA1 = acc[mi][ni][1] + b1;
                float vB0 = acc[mi][ni][2] + b0;
                float vB1 = acc[mi][ni][3] + b1;
#pragma unroll
                for (int h = 0; h < 8; h++) {
                    float w0 = w2s[h * 256 + c0], w1 = w2s[h * 256 + c1];
                    vA0 += mA[h] * w0; vA1 += mA[h] * w1;
                    vB0 += mB[h] * w0; vB1 += mB[h] * w1;
                }
                vA0 = leaky(vA0); vA1 = leaky(vA1);
                vB0 = leaky(vB0); vB1 = leaky(vB1);
                uint32_t hi, lo;
                split2h(vA0, vA1, hi, lo);
                *(uint32_t*)(sm + IH + rA * 528 + c0 * 2) = hi;
                *(uint32_t*)(sm + IL + rA * 528 + c0 * 2) = lo;
                split2h(vB0, vB1, hi, lo);
                *(uint32_t*)(sm + IH + rB * 528 + c0 * 2) = hi;
                *(uint32_t*)(sm + IL + rB * 528 + c0 * 2) = lo;
                acc[mi][ni][0] = 0.f; acc[mi][ni][1] = 0.f;
                acc[mi][ni][2] = 0.f; acc[mi][ni][3] = 0.f;
            }
        }
    }

    // ================= GEMM2: inter @ Wa =================
#pragma unroll
    for (int ci = 0; ci < 4; ci++) {
        pfB(g_WaT, ci * 64);
        CP_COMMIT();
        CP_WAIT(0);
        __syncthreads();
        gemm_chunk(acc, sb + IH + ci * 128, sb + IL + ci * 128, 528,
                   sb + BO, wm, wn, lane);
        __syncthreads();
    }

    // ====== epilogue2: + ba -> stage -> coalesced store ======
    {
        float* stage = (float*)(sm + IH);   // 64*264*4 = 67584, spans IH+IL
        const int g = lane >> 2, t = lane & 3;
#pragma unroll
        for (int mi = 0; mi < 2; mi++) {
            const int rA = wm * 32 + mi * 16 + g, rB = rA + 8;
#pragma unroll
            for (int ni = 0; ni < 8; ni++) {
                const int c0 = wn * 64 + ni * 8 + 2 * t;
                float b0 = bap[c0], b1 = bap[c0 + 1];
                *(float2*)(stage + rA * 264 + c0) = make_float2(acc[mi][ni][0] + b0, acc[mi][ni][1] + b1);
                *(float2*)(stage + rB * 264 + c0) = make_float2(acc[mi][ni][2] + b0, acc[mi][ni][3] + b1);
            }
        }
        __syncthreads();
        for (int idx = tid; idx < 64 * 64; idx += 256) {
            int r = idx >> 6, c4 = (idx & 63) << 2;
            int node = row0 + r;
            if (node < N_NODES)
                *(float4*)(out + (size_t)node * 256 + c4) = *(const float4*)(stage + r * 264 + c4);
        }
    }
}

// ---------------- launch ----------------
extern "C" void kernel_launch(void* const* d_in, const int* in_sizes, int n_in,
                              void* d_out, int out_size) {
    const float* feat  = (const float*)d_in[0];
    const float* fedge = (const float*)d_in[1];
    const int*   src   = (const int*)d_in[2];
    const int*   dst   = (const int*)d_in[3];
    const float* Wp    = (const float*)d_in[4];
    const float* Was   = (const float*)d_in[5];
    const float* Wad   = (const float*)d_in[6];
    const float* Wae   = (const float*)d_in[7];
    const float* gamma = (const float*)d_in[8];
    const float* beta  = (const float*)d_in[9];
    const float* Wagg  = (const float*)d_in[10];
    const float* bagg  = (const float*)d_in[11];
    const float* Wapd  = (const float*)d_in[12];
    const float* bapd  = (const float*)d_in[13];
    const float* Wap   = (const float*)d_in[14];
    const float* bap   = (const float*)d_in[15];
    float* out = (float*)d_out;

    k_node<<<N_NODES / 32, 256>>>(feat, Wp, Was, Wad);
    k_split<<<dim3(8, 8, 2), dim3(32, 8)>>>(Wapd, Wap);
    k_edge1<<<(N_EDGES + 255) / 256, 256>>>(fedge, src, dst, Wae);
    k_rs<<<(N_NODES * N_HEAD + 255) / 256, 256>>>();
    k_edge2<<<(N_EDGES + 255) / 256, 256>>>(src, dst);
    k_stats<<<(N_NODES + 255) / 256, 256>>>();
    k_prep<<<1, 256>>>(gamma, beta, Wagg, bagg, bapd);

    cudaFuncSetAttribute(k_tc, cudaFuncAttributeMaxDynamicSharedMemorySize, TC_SMEM);
    k_tc<<<N_TILES, 256, TC_SMEM>>>(bap, out);
}

// round 14
// speedup vs baseline: 1.9542x; 1.1398x over previous
#include <cuda_runtime.h>
#include <cuda_bf16.h>
#include <cuda_fp16.h>
#include <cstdint>
#include <cstddef>

#define N_NODES 100000
#define N_EDGES 3200000
#define NODE_F  256
#define EDGE_F  16
#define N_HEAD  8
#define OUT_F   256
#define N_TILES 1563   // ceil(100000/64)

// ---------------- scratch (static device globals; no allocation) ----------------
__device__ __align__(16) float g_fc[N_NODES * N_HEAD];
__device__ __align__(16) float g_as[N_NODES * N_HEAD];
__device__ __align__(16) float g_ad[N_NODES * N_HEAD];
__device__ __align__(16) __nv_bfloat16 g_eexp[(size_t)N_EDGES * N_HEAD];  // 51.2 MB packed
__device__ __align__(16) float g_sumd[N_NODES * N_HEAD];
__device__ __align__(16) float g_sums[N_NODES * N_HEAD];
__device__ __align__(16) float g_msg[N_NODES * N_HEAD];
__device__ __align__(16) float g_stats[2 * N_HEAD];
__device__ __align__(16) float g_w2[N_HEAD * OUT_F];
__device__ __align__(16) float g_b2[OUT_F];
// fp16-rounded features (single-product scheme)
__device__ __align__(16) __half g_fh[(size_t)N_NODES * NODE_F];
// transposed weights: [n][k] = W[k][n], single fp16
__device__ __align__(16) __half g_WdT[256 * 256];
__device__ __align__(16) __half g_WaT[256 * 256];

// ---------------- helpers ----------------
__device__ __forceinline__ void red4(float* p, float a, float b, float c, float d) {
    asm volatile("red.global.add.v4.f32 [%0], {%1, %2, %3, %4};"
                 :: "l"(p), "f"(a), "f"(b), "f"(c), "f"(d) : "memory");
}
__device__ __forceinline__ float leaky(float x) { return x >= 0.f ? x : 0.2f * x; }

__device__ __forceinline__ uint32_t smem_u32(const void* p) {
    uint32_t a;
    asm("{ .reg .u64 t; cvta.to.shared.u64 t, %1; cvt.u32.u64 %0, t; }" : "=r"(a) : "l"(p));
    return a;
}
__device__ __forceinline__ uint32_t pack2h(float a, float b) {
    __half2 h = __floats2half2_rn(a, b);
    return *reinterpret_cast<uint32_t*>(&h);
}
__device__ __forceinline__ void ldsm4(uint32_t a, uint32_t r[4]) {
    asm volatile("ldmatrix.sync.aligned.m8n8.x4.shared.b16 {%0,%1,%2,%3}, [%4];"
                 : "=r"(r[0]), "=r"(r[1]), "=r"(r[2]), "=r"(r[3]) : "r"(a));
}
__device__ __forceinline__ void mma16816(float c[4], const uint32_t a[4], uint32_t b0, uint32_t b1) {
    asm volatile("mma.sync.aligned.m16n8k16.row.col.f32.f16.f16.f32 "
                 "{%0,%1,%2,%3}, {%4,%5,%6,%7}, {%8,%9}, {%0,%1,%2,%3};"
                 : "+f"(c[0]), "+f"(c[1]), "+f"(c[2]), "+f"(c[3])
                 : "r"(a[0]), "r"(a[1]), "r"(a[2]), "r"(a[3]), "r"(b0), "r"(b1));
}
__device__ __forceinline__ void cpa16(uint32_t dst, const void* src) {
    asm volatile("cp.async.cg.shared.global [%0], [%1], 16;" :: "r"(dst), "l"(src));
}
#define CP_COMMIT() asm volatile("cp.async.commit_group;" ::: "memory")
#define CP_WAIT(n)  asm volatile("cp.async.wait_group %0;" :: "n"(n) : "memory")

// ---------------- K1: node linear 256->24 + zero-init + fp16 feature round ----------------
__global__ __launch_bounds__(256) void k_node(const float* __restrict__ feat,
                                              const float* __restrict__ Wp,
                                              const float* __restrict__ Was,
                                              const float* __restrict__ Wad) {
    __shared__ float Ws[256 * 24];
    __shared__ float fs[32 * 260];
    int tid = threadIdx.x;
    int row0 = blockIdx.x * 32;
    {
        int o = row0 * 8 + tid;
        g_sumd[o] = 0.f; g_sums[o] = 0.f; g_msg[o] = 0.f;
        if (blockIdx.x == 0 && tid < 16) g_stats[tid] = 0.f;
    }
    for (int i = tid; i < 256 * 8; i += 256) {
        int k = i >> 3, h = i & 7;
        Ws[k * 24 + h]      = Wp[i];
        Ws[k * 24 + 8 + h]  = Was[i];
        Ws[k * 24 + 16 + h] = Wad[i];
    }
    for (int i = tid; i < 32 * 256; i += 256) {
        int r = i >> 8, c = i & 255;
        fs[r * 260 + c] = feat[(size_t)(row0 + r) * 256 + c];
    }
    __syncthreads();
    // fp16 round of features (single-product GEMM A operand)
    for (int i = tid; i < 32 * 128; i += 256) {
        int r = i >> 7, c2 = (i & 127) * 2;
        ((uint32_t*)g_fh)[((size_t)(row0 + r) * 256 + c2) >> 1] =
            pack2h(fs[r * 260 + c2], fs[r * 260 + c2 + 1]);
    }
    int r = tid >> 3, h = tid & 7;
    const float* fr = fs + r * 260;
    float a0 = 0.f, a1 = 0.f, a2 = 0.f;
#pragma unroll 8
    for (int k = 0; k < 256; k++) {
        float f = fr[k];
        a0 += f * Ws[k * 24 + h];
        a1 += f * Ws[k * 24 + 8 + h];
        a2 += f * Ws[k * 24 + 16 + h];
    }
    int n = row0 + r;
    g_fc[n * 8 + h] = a0;
    g_as[n * 8 + h] = a1;
    g_ad[n * 8 + h] = a2;
}

// ---------------- K1b: transpose + fp16-round weights ----------------
__global__ void k_split(const float* __restrict__ Wd, const float* __restrict__ Wa) {
    __shared__ float t[32][33];
    const float* W = blockIdx.z ? Wa : Wd;
    __half* O = blockIdx.z ? g_WaT : g_WdT;
    int kb = blockIdx.x * 32, nb = blockIdx.y * 32;
    int tx = threadIdx.x;
    for (int ty = threadIdx.y; ty < 32; ty += 8)
        t[ty][tx] = W[(size_t)(kb + ty) * 256 + nb + tx];
    __syncthreads();
    for (int ty = threadIdx.y; ty < 32; ty += 8)
        O[(size_t)(nb + ty) * 256 + kb + tx] = __float2half_rn(t[tx][ty]);
}

// ---------------- K2: edge attention, exp, scatter sums ----------------
__global__ __launch_bounds__(256) void k_edge1(const float* __restrict__ fe,
                                               const int* __restrict__ src,
                                               const int* __restrict__ dst,
                                               const float* __restrict__ Wae) {
    __shared__ float4 Wv[32];
    int tid = threadIdx.x;
    if (tid < 32) Wv[tid] = ((const float4*)Wae)[tid];
    __syncthreads();
    int e = blockIdx.x * 256 + tid;
    if (e >= N_EDGES) return;
    int s = src[e], d = dst[e];

    const float4* fp = (const float4*)(fe + (size_t)e * 16);
    float4 f0 = fp[0], f1 = fp[1], f2 = fp[2], f3 = fp[3];

    float v[8];
    {
        const float4* ap = (const float4*)(g_as + (size_t)s * 8);
        const float4* bp = (const float4*)(g_ad + (size_t)d * 8);
        float4 a0 = ap[0], a1 = ap[1], b0 = bp[0], b1 = bp[1];
        v[0] = a0.x + b0.x; v[1] = a0.y + b0.y; v[2] = a0.z + b0.z; v[3] = a0.w + b0.w;
        v[4] = a1.x + b1.x; v[5] = a1.y + b1.y; v[6] = a1.z + b1.z; v[7] = a1.w + b1.w;
    }
#define ADDK(F, K) { float4 wa = Wv[2*(K)], wb = Wv[2*(K)+1]; \
    v[0] += (F)*wa.x; v[1] += (F)*wa.y; v[2] += (F)*wa.z; v[3] += (F)*wa.w; \
    v[4] += (F)*wb.x; v[5] += (F)*wb.y; v[6] += (F)*wb.z; v[7] += (F)*wb.w; }
    ADDK(f0.x, 0)  ADDK(f0.y, 1)  ADDK(f0.z, 2)  ADDK(f0.w, 3)
    ADDK(f1.x, 4)  ADDK(f1.y, 5)  ADDK(f1.z, 6)  ADDK(f1.w, 7)
    ADDK(f2.x, 8)  ADDK(f2.y, 9)  ADDK(f2.z, 10) ADDK(f2.w, 11)
    ADDK(f3.x, 12) ADDK(f3.y, 13) ADDK(f3.z, 14) ADDK(f3.w, 15)
#undef ADDK

    float ex[8];
#pragma unroll
    for (int h = 0; h < 8; h++) ex[h] = __expf(leaky(v[h]));

    __nv_bfloat162 p[4];
    p[0] = __floats2bfloat162_rn(ex[0], ex[1]);
    p[1] = __floats2bfloat162_rn(ex[2], ex[3]);
    p[2] = __floats2bfloat162_rn(ex[4], ex[5]);
    p[3] = __floats2bfloat162_rn(ex[6], ex[7]);
    *(uint4*)(g_eexp + (size_t)e * 8) = *reinterpret_cast<uint4*>(p);

    red4(g_sumd + (size_t)d * 8,     ex[0], ex[1], ex[2], ex[3]);
    red4(g_sumd + (size_t)d * 8 + 4, ex[4], ex[5], ex[6], ex[7]);
    red4(g_sums + (size_t)s * 8,     ex[0], ex[1], ex[2], ex[3]);
    red4(g_sums + (size_t)s * 8 + 4, ex[4], ex[5], ex[6], ex[7]);
}

// ---------------- K2b: per-node strength reduction (in-place) ----------------
__global__ __launch_bounds__(256) void k_rs() {
    int i = blockIdx.x * 256 + threadIdx.x;
    if (i < N_NODES * N_HEAD) {
        g_sumd[i] = rsqrtf(g_sumd[i]);
        g_fc[i] *= rsqrtf(g_sums[i]);
    }
}

// ---------------- K3: dual-softmax coeff + message scatter ----------------
__global__ __launch_bounds__(256) void k_edge2(const int* __restrict__ src,
                                               const int* __restrict__ dst) {
    int e = blockIdx.x * 256 + threadIdx.x;
    if (e >= N_EDGES) return;
    int s = src[e], d = dst[e];
    uint4 raw = *(const uint4*)(g_eexp + (size_t)e * 8);
    const __nv_bfloat162* pr = reinterpret_cast<const __nv_bfloat162*>(&raw);
    float2 e01 = __bfloat1622float2(pr[0]);
    float2 e23 = __bfloat1622float2(pr[1]);
    float2 e45 = __bfloat1622float2(pr[2]);
    float2 e67 = __bfloat1622float2(pr[3]);
    const float4* sdp = (const float4*)(g_sumd + (size_t)d * 8);   // rsqrt(sumd)
    const float4* fcp = (const float4*)(g_fc   + (size_t)s * 8);   // fc * rsqrt(sums)
    float4 sd0 = sdp[0], sd1 = sdp[1];
    float4 c0 = fcp[0], c1 = fcp[1];

    float m0 = e01.x * sd0.x * c0.x;
    float m1 = e01.y * sd0.y * c0.y;
    float m2 = e23.x * sd0.z * c0.z;
    float m3 = e23.y * sd0.w * c0.w;
    float m4 = e45.x * sd1.x * c1.x;
    float m5 = e45.y * sd1.y * c1.y;
    float m6 = e67.x * sd1.z * c1.z;
    float m7 = e67.y * sd1.w * c1.w;

    red4(g_msg + (size_t)d * 8,     m0, m1, m2, m3);
    red4(g_msg + (size_t)d * 8 + 4, m4, m5, m6, m7);
}

// ---------------- K4: BN statistics ----------------
__global__ __launch_bounds__(256) void k_stats() {
    int n = blockIdx.x * 256 + threadIdx.x;
    float a[8], q[8];
#pragma unroll
    for (int h = 0; h < 8; h++) { a[h] = 0.f; q[h] = 0.f; }
    if (n < N_NODES) {
        const float4* mp = (const float4*)(g_msg + (size_t)n * 8);
        float4 m0 = mp[0], m1 = mp[1];
        a[0] = m0.x; a[1] = m0.y; a[2] = m0.z; a[3] = m0.w;
        a[4] = m1.x; a[5] = m1.y; a[6] = m1.z; a[7] = m1.w;
#pragma unroll
        for (int h = 0; h < 8; h++) q[h] = a[h] * a[h];
    }
#pragma unroll
    for (int h = 0; h < 8; h++) {
        for (int off = 16; off; off >>= 1) {
            a[h] += __shfl_xor_sync(0xFFFFFFFFu, a[h], off);
            q[h] += __shfl_xor_sync(0xFFFFFFFFu, q[h], off);
        }
    }
    if ((threadIdx.x & 31) == 0) {
#pragma unroll
        for (int h = 0; h < 8; h++) {
            atomicAdd(&g_stats[h], a[h]);
            atomicAdd(&g_stats[8 + h], q[h]);
        }
    }
}

// ---------------- K5: fold BN + W_agg + b_apply_dst into W2 / b2 ----------------
__global__ void k_prep(const float* __restrict__ gamma, const float* __restrict__ beta,
                       const float* __restrict__ Wagg, const float* __restrict__ bagg,
                       const float* __restrict__ bapd) {
    __shared__ float sc[8], sh[8];
    int tid = threadIdx.x;
    if (tid < 8) {
        float mu  = g_stats[tid] * (1.f / N_NODES);
        float var = g_stats[8 + tid] * (1.f / N_NODES) - mu * mu;
        float s = gamma[tid] * rsqrtf(var + 1e-5f);
        sc[tid] = s;
        sh[tid] = beta[tid] - mu * s;
    }
    __syncthreads();
    int c = tid;
    float b = bagg[c] + bapd[c];
#pragma unroll
    for (int h = 0; h < 8; h++) {
        float w = Wagg[h * 256 + c];
        g_w2[h * 256 + c] = sc[h] * w;
        b += sh[h] * w;
    }
    g_b2[c] = b;
}

// ---------------- K6: fused double GEMM, single-fp16 operands, 64-row CTA, 2 CTAs/SM ----
#define IH    0         // A1 chunk (stride 144) / inter fp16 (stride 528, 33792) / epi2 stage part
#define BO    33792     // B single buffer 256*144 = 36864
#define W2O   70656     // w2 8*256*4 = 8192
#define MSO   78848     // msgs 64*8*4 = 2048
#define TC_SMEM 80896   // 2 CTAs/SM

__device__ __forceinline__ void gemm_chunk(float acc[2][8][4],
                                           uint32_t aB, uint32_t astride,
                                           uint32_t bB, int wm, int wn, int lane) {
    const uint32_t arow = (uint32_t)(wm * 32 + (lane & 15));
    const uint32_t akh  = (uint32_t)((lane >> 4) * 8);
    const uint32_t brow = (uint32_t)(wn * 64 + (lane & 7) + ((lane >> 4) & 1) * 8);
    const uint32_t bkh  = (uint32_t)(((lane >> 3) & 1) * 8);
#pragma unroll
    for (int ks = 0; ks < 64; ks += 16) {
        uint32_t a[2][4];
#pragma unroll
        for (int mi = 0; mi < 2; mi++) {
            uint32_t ao = (arow + mi * 16) * astride + (ks + akh) * 2;
            ldsm4(aB + ao, a[mi]);
        }
#pragma unroll
        for (int nip = 0; nip < 4; nip++) {
            uint32_t bo = (brow + nip * 16) * 144 + (ks + bkh) * 2;
            uint32_t b[4];
            ldsm4(bB + bo, b);
#pragma unroll
            for (int mi = 0; mi < 2; mi++) {
                mma16816(acc[mi][nip * 2],     a[mi], b[0], b[1]);
                mma16816(acc[mi][nip * 2 + 1], a[mi], b[2], b[3]);
            }
        }
    }
}

__global__ void __launch_bounds__(256, 2) k_tc(const float* __restrict__ bap,
                                               float* __restrict__ out) {
    extern __shared__ char sm[];
    const uint32_t sb = smem_u32(sm);
    const int tid = threadIdx.x;
    const int warp = tid >> 5, lane = tid & 31;
    const int wm = warp >> 2, wn = warp & 3;
    const int row0 = blockIdx.x * 64;

    float* w2s  = (float*)(sm + W2O);
    float* msgs = (float*)(sm + MSO);

    auto pfA = [&](int kc) {
#pragma unroll
        for (int i = tid; i < 512; i += 256) {
            int r = i >> 3, s = i & 7;
            int node = row0 + r; if (node >= N_NODES) node = N_NODES - 1;
            cpa16(sb + IH + (uint32_t)(r * 144 + s * 16),
                  g_fh + (size_t)node * 256 + kc + s * 8);
        }
    };
    auto pfB = [&](const __half* W, int kc) {
#pragma unroll
        for (int i = tid; i < 2048; i += 256) {
            int n = i >> 3, s = i & 7;
            cpa16(sb + BO + (uint32_t)(n * 144 + s * 16), W + (size_t)n * 256 + kc + s * 8);
        }
    };

    for (int i = tid; i < 2048; i += 256) w2s[i] = g_w2[i];
    for (int i = tid; i < 512; i += 256) {
        int r = i >> 3;
        int node = row0 + r; if (node >= N_NODES) node = N_NODES - 1;
        msgs[i] = g_msg[(size_t)node * 8 + (i & 7)];
    }

    float acc[2][8][4];
#pragma unroll
    for (int mi = 0; mi < 2; mi++)
#pragma unroll
        for (int ni = 0; ni < 8; ni++)
#pragma unroll
            for (int j = 0; j < 4; j++) acc[mi][ni][j] = 0.f;

    // ================= GEMM1: feat(fp16) @ WdT =================
#pragma unroll
    for (int ci = 0; ci < 4; ci++) {
        pfA(ci * 64);
        pfB(g_WdT, ci * 64);
        CP_COMMIT();
        CP_WAIT(0);
        __syncthreads();
        gemm_chunk(acc, sb + IH, 144, sb + BO, wm, wn, lane);
        __syncthreads();
    }

    // ====== epilogue1: + bias + msg@W2, leaky, fp16 round -> inter (stride 528B) ======
    {
        const int g = lane >> 2, t = lane & 3;
#pragma unroll
        for (int mi = 0; mi < 2; mi++) {
            const int rA = wm * 32 + mi * 16 + g, rB = rA + 8;
            float mA[8], mB[8];
#pragma unroll
            for (int h = 0; h < 8; h++) { mA[h] = msgs[rA * 8 + h]; mB[h] = msgs[rB * 8 + h]; }
#pragma unroll
            for (int ni = 0; ni < 8; ni++) {
                const int c0 = wn * 64 + ni * 8 + 2 * t, c1 = c0 + 1;
                float b0 = g_b2[c0], b1 = g_b2[c1];
                float vA0 = acc[mi][ni][0] + b0;
                float vA1 = acc[mi][ni][1] + b1;
                float vB0 = acc[mi][ni][2] + b0;
                float vB1 = acc[mi][ni][3] + b1;
#pragma unroll
                for (int h = 0; h < 8; h++) {
                    float w0 = w2s[h * 256 + c0], w1 = w2s[h * 256 + c1];
                    vA0 += mA[h] * w0; vA1 += mA[h] * w1;
                    vB0 += mB[h] * w0; vB1 += mB[h] * w1;
                }
                *(uint32_t*)(sm + IH + rA * 528 + c0 * 2) = pack2h(leaky(vA0), leaky(vA1));
                *(uint32_t*)(sm + IH + rB * 528 + c0 * 2) = pack2h(leaky(vB0), leaky(vB1));
                acc[mi][ni][0] = 0.f; acc[mi][ni][1] = 0.f;
                acc[mi][ni][2] = 0.f; acc[mi][ni][3] = 0.f;
            }
        }
    }

    // ================= GEMM2: inter(fp16) @ WaT =================
#pragma unroll
    for (int ci = 0; ci < 4; ci++) {
        pfB(g_WaT, ci * 64);
        CP_COMMIT();
        CP_WAIT(0);
        __syncthreads();
        gemm_chunk(acc, sb + IH + ci * 128, 528, sb + BO, wm, wn, lane);
        __syncthreads();
    }

    // ====== epilogue2: + ba -> stage (fp32, stride 264 floats) -> coalesced store ======
    {
        float* stage = (float*)(sm + IH);   // 64*264*4 = 67584, spans IH+BO (both dead now)
        const int g = lane >> 2, t = lane & 3;
#pragma unroll
        for (int mi = 0; mi < 2; mi++) {
            const int rA = wm * 32 + mi * 16 + g, rB = rA + 8;
#pragma unroll
            for (int ni = 0; ni < 8; ni++) {
                const int c0 = wn * 64 + ni * 8 + 2 * t;
                float b0 = bap[c0], b1 = bap[c0 + 1];
                *(float2*)(stage + rA * 264 + c0) = make_float2(acc[mi][ni][0] + b0, acc[mi][ni][1] + b1);
                *(float2*)(stage + rB * 264 + c0) = make_float2(acc[mi][ni][2] + b0, acc[mi][ni][3] + b1);
            }
        }
        __syncthreads();
        for (int idx = tid; idx < 64 * 64; idx += 256) {
            int r = idx >> 6, c4 = (idx & 63) << 2;
            int node = row0 + r;
            if (node < N_NODES)
                *(float4*)(out + (size_t)node * 256 + c4) = *(const float4*)(stage + r * 264 + c4);
        }
    }
}

// ---------------- launch ----------------
extern "C" void kernel_launch(void* const* d_in, const int* in_sizes, int n_in,
                              void* d_out, int out_size) {
    const float* feat  = (const float*)d_in[0];
    const float* fedge = (const float*)d_in[1];
    const int*   src   = (const int*)d_in[2];
    const int*   dst   = (const int*)d_in[3];
    const float* Wp    = (const float*)d_in[4];
    const float* Was   = (const float*)d_in[5];
    const float* Wad   = (const float*)d_in[6];
    const float* Wae   = (const float*)d_in[7];
    const float* gamma = (const float*)d_in[8];
    const float* beta  = (const float*)d_in[9];
    const float* Wagg  = (const float*)d_in[10];
    const float* bagg  = (const float*)d_in[11];
    const float* Wapd  = (const float*)d_in[12];
    const float* bapd  = (const float*)d_in[13];
    const float* Wap   = (const float*)d_in[14];
    const float* bap   = (const float*)d_in[15];
    float* out = (float*)d_out;

    k_node<<<N_NODES / 32, 256>>>(feat, Wp, Was, Wad);
    k_split<<<dim3(8, 8, 2), dim3(32, 8)>>>(Wapd, Wap);
    k_edge1<<<(N_EDGES + 255) / 256, 256>>>(fedge, src, dst, Wae);
    k_rs<<<(N_NODES * N_HEAD + 255) / 256, 256>>>();
    k_edge2<<<(N_EDGES + 255) / 256, 256>>>(src, dst);
    k_stats<<<(N_NODES + 255) / 256, 256>>>();
    k_prep<<<1, 256>>>(gamma, beta, Wagg, bagg, bapd);

    cudaFuncSetAttribute(k_tc, cudaFuncAttributeMaxDynamicSharedMemorySize, TC_SMEM);
    k_tc<<<N_TILES, 256, TC_SMEM>>>(bap, out);
}

// round 15
// speedup vs baseline: 2.0091x; 1.0281x over previous
#include <cuda_runtime.h>
#include <cuda_bf16.h>
#include <cuda_fp16.h>
#include <cstdint>
#include <cstddef>

#define N_NODES 100000
#define N_EDGES 3200000
#define NODE_F  256
#define EDGE_F  16
#define N_HEAD  8
#define OUT_F   256
#define N_TILES 1563   // ceil(100000/64)

// ---------------- scratch (static device globals; no allocation) ----------------
__device__ __align__(16) float g_fc[N_NODES * N_HEAD];
__device__ __align__(16) __half g_ash[N_NODES * N_HEAD];   // attn_src fp16 (16B/node gathers)
__device__ __align__(16) __half g_adh[N_NODES * N_HEAD];   // attn_dst fp16
__device__ __align__(16) __nv_bfloat16 g_eexp[(size_t)N_EDGES * N_HEAD];  // 51.2 MB packed
__device__ __align__(16) float g_sumd[N_NODES * N_HEAD];
__device__ __align__(16) float g_sums[N_NODES * N_HEAD];
__device__ __align__(16) __half g_sdh[N_NODES * N_HEAD];   // fp16(rsqrt(sumd))
__device__ __align__(16) __half g_fch[N_NODES * N_HEAD];   // fp16(fc * rsqrt(sums))
__device__ __align__(16) float g_msg[N_NODES * N_HEAD];
__device__ __align__(16) float g_stats[2 * N_HEAD];
__device__ __align__(16) float g_w2[N_HEAD * OUT_F];
__device__ __align__(16) float g_b2[OUT_F];
// fp16-rounded features (single-product scheme)
__device__ __align__(16) __half g_fh[(size_t)N_NODES * NODE_F];
// transposed weights: [n][k] = W[k][n], single fp16
__device__ __align__(16) __half g_WdT[256 * 256];
__device__ __align__(16) __half g_WaT[256 * 256];

// ---------------- helpers ----------------
__device__ __forceinline__ void red4(float* p, float a, float b, float c, float d) {
    asm volatile("red.global.add.v4.f32 [%0], {%1, %2, %3, %4};"
                 :: "l"(p), "f"(a), "f"(b), "f"(c), "f"(d) : "memory");
}
__device__ __forceinline__ float leaky(float x) { return x >= 0.f ? x : 0.2f * x; }

__device__ __forceinline__ uint32_t smem_u32(const void* p) {
    uint32_t a;
    asm("{ .reg .u64 t; cvta.to.shared.u64 t, %1; cvt.u32.u64 %0, t; }" : "=r"(a) : "l"(p));
    return a;
}
__device__ __forceinline__ uint32_t pack2h(float a, float b) {
    __half2 h = __floats2half2_rn(a, b);
    return *reinterpret_cast<uint32_t*>(&h);
}
__device__ __forceinline__ void unpk8h(const uint4& r, float f[8]) {
    const __half2* h = reinterpret_cast<const __half2*>(&r);
    float2 p0 = __half22float2(h[0]);
    float2 p1 = __half22float2(h[1]);
    float2 p2 = __half22float2(h[2]);
    float2 p3 = __half22float2(h[3]);
    f[0] = p0.x; f[1] = p0.y; f[2] = p1.x; f[3] = p1.y;
    f[4] = p2.x; f[5] = p2.y; f[6] = p3.x; f[7] = p3.y;
}
__device__ __forceinline__ void ldsm4(uint32_t a, uint32_t r[4]) {
    asm volatile("ldmatrix.sync.aligned.m8n8.x4.shared.b16 {%0,%1,%2,%3}, [%4];"
                 : "=r"(r[0]), "=r"(r[1]), "=r"(r[2]), "=r"(r[3]) : "r"(a));
}
__device__ __forceinline__ void mma16816(float c[4], const uint32_t a[4], uint32_t b0, uint32_t b1) {
    asm volatile("mma.sync.aligned.m16n8k16.row.col.f32.f16.f16.f32 "
                 "{%0,%1,%2,%3}, {%4,%5,%6,%7}, {%8,%9}, {%0,%1,%2,%3};"
                 : "+f"(c[0]), "+f"(c[1]), "+f"(c[2]), "+f"(c[3])
                 : "r"(a[0]), "r"(a[1]), "r"(a[2]), "r"(a[3]), "r"(b0), "r"(b1));
}
__device__ __forceinline__ void cpa16(uint32_t dst, const void* src) {
    asm volatile("cp.async.cg.shared.global [%0], [%1], 16;" :: "r"(dst), "l"(src));
}
#define CP_COMMIT() asm volatile("cp.async.commit_group;" ::: "memory")
#define CP_WAIT(n)  asm volatile("cp.async.wait_group %0;" :: "n"(n) : "memory")

// ---------------- K1: node linear 256->24 + zero-init + fp16 feature round ----------------
__global__ __launch_bounds__(256) void k_node(const float* __restrict__ feat,
                                              const float* __restrict__ Wp,
                                              const float* __restrict__ Was,
                                              const float* __restrict__ Wad) {
    __shared__ float Ws[256 * 24];
    __shared__ float fs[32 * 260];
    int tid = threadIdx.x;
    int row0 = blockIdx.x * 32;
    {
        int o = row0 * 8 + tid;
        g_sumd[o] = 0.f; g_sums[o] = 0.f; g_msg[o] = 0.f;
        if (blockIdx.x == 0 && tid < 16) g_stats[tid] = 0.f;
    }
    for (int i = tid; i < 256 * 8; i += 256) {
        int k = i >> 3, h = i & 7;
        Ws[k * 24 + h]      = Wp[i];
        Ws[k * 24 + 8 + h]  = Was[i];
        Ws[k * 24 + 16 + h] = Wad[i];
    }
    for (int i = tid; i < 32 * 256; i += 256) {
        int r = i >> 8, c = i & 255;
        fs[r * 260 + c] = feat[(size_t)(row0 + r) * 256 + c];
    }
    __syncthreads();
    // fp16 round of features (single-product GEMM A operand)
    for (int i = tid; i < 32 * 128; i += 256) {
        int r = i >> 7, c2 = (i & 127) * 2;
        ((uint32_t*)g_fh)[((size_t)(row0 + r) * 256 + c2) >> 1] =
            pack2h(fs[r * 260 + c2], fs[r * 260 + c2 + 1]);
    }
    int r = tid >> 3, h = tid & 7;
    const float* fr = fs + r * 260;
    float a0 = 0.f, a1 = 0.f, a2 = 0.f;
#pragma unroll 8
    for (int k = 0; k < 256; k++) {
        float f = fr[k];
        a0 += f * Ws[k * 24 + h];
        a1 += f * Ws[k * 24 + 8 + h];
        a2 += f * Ws[k * 24 + 16 + h];
    }
    int n = row0 + r;
    g_fc[n * 8 + h]  = a0;
    g_ash[n * 8 + h] = __float2half_rn(a1);
    g_adh[n * 8 + h] = __float2half_rn(a2);
}

// ---------------- K1b: transpose + fp16-round weights ----------------
__global__ void k_split(const float* __restrict__ Wd, const float* __restrict__ Wa) {
    __shared__ float t[32][33];
    const float* W = blockIdx.z ? Wa : Wd;
    __half* O = blockIdx.z ? g_WaT : g_WdT;
    int kb = blockIdx.x * 32, nb = blockIdx.y * 32;
    int tx = threadIdx.x;
    for (int ty = threadIdx.y; ty < 32; ty += 8)
        t[ty][tx] = W[(size_t)(kb + ty) * 256 + nb + tx];
    __syncthreads();
    for (int ty = threadIdx.y; ty < 32; ty += 8)
        O[(size_t)(nb + ty) * 256 + kb + tx] = __float2half_rn(t[tx][ty]);
}

// ---------------- K2: edge attention, exp, scatter sums ----------------
__global__ __launch_bounds__(256) void k_edge1(const float* __restrict__ fe,
                                               const int* __restrict__ src,
                                               const int* __restrict__ dst,
                                               const float* __restrict__ Wae) {
    __shared__ float4 Wv[32];
    int tid = threadIdx.x;
    if (tid < 32) Wv[tid] = ((const float4*)Wae)[tid];
    __syncthreads();
    int e = blockIdx.x * 256 + tid;
    if (e >= N_EDGES) return;
    int s = src[e], d = dst[e];

    const float4* fp = (const float4*)(fe + (size_t)e * 16);
    float4 f0 = fp[0], f1 = fp[1], f2 = fp[2], f3 = fp[3];

    float v[8];
    {
        uint4 ra = *(const uint4*)(g_ash + (size_t)s * 8);   // 16B gather
        uint4 rb = *(const uint4*)(g_adh + (size_t)d * 8);   // 16B gather
        float av[8], bv[8];
        unpk8h(ra, av);
        unpk8h(rb, bv);
#pragma unroll
        for (int h = 0; h < 8; h++) v[h] = av[h] + bv[h];
    }
#define ADDK(F, K) { float4 wa = Wv[2*(K)], wb = Wv[2*(K)+1]; \
    v[0] += (F)*wa.x; v[1] += (F)*wa.y; v[2] += (F)*wa.z; v[3] += (F)*wa.w; \
    v[4] += (F)*wb.x; v[5] += (F)*wb.y; v[6] += (F)*wb.z; v[7] += (F)*wb.w; }
    ADDK(f0.x, 0)  ADDK(f0.y, 1)  ADDK(f0.z, 2)  ADDK(f0.w, 3)
    ADDK(f1.x, 4)  ADDK(f1.y, 5)  ADDK(f1.z, 6)  ADDK(f1.w, 7)
    ADDK(f2.x, 8)  ADDK(f2.y, 9)  ADDK(f2.z, 10) ADDK(f2.w, 11)
    ADDK(f3.x, 12) ADDK(f3.y, 13) ADDK(f3.z, 14) ADDK(f3.w, 15)
#undef ADDK

    float ex[8];
#pragma unroll
    for (int h = 0; h < 8; h++) ex[h] = __expf(leaky(v[h]));

    __nv_bfloat162 p[4];
    p[0] = __floats2bfloat162_rn(ex[0], ex[1]);
    p[1] = __floats2bfloat162_rn(ex[2], ex[3]);
    p[2] = __floats2bfloat162_rn(ex[4], ex[5]);
    p[3] = __floats2bfloat162_rn(ex[6], ex[7]);
    *(uint4*)(g_eexp + (size_t)e * 8) = *reinterpret_cast<uint4*>(p);

    red4(g_sumd + (size_t)d * 8,     ex[0], ex[1], ex[2], ex[3]);
    red4(g_sumd + (size_t)d * 8 + 4, ex[4], ex[5], ex[6], ex[7]);
    red4(g_sums + (size_t)s * 8,     ex[0], ex[1], ex[2], ex[3]);
    red4(g_sums + (size_t)s * 8 + 4, ex[4], ex[5], ex[6], ex[7]);
}

// ---------------- K2b: per-node strength reduction -> packed fp16 gather operands ------
__global__ __launch_bounds__(256) void k_rs() {
    int i = blockIdx.x * 256 + threadIdx.x;
    if (i < N_NODES * N_HEAD) {
        g_sdh[i] = __float2half_rn(rsqrtf(g_sumd[i]));
        g_fch[i] = __float2half_rn(g_fc[i] * rsqrtf(g_sums[i]));
    }
}

// ---------------- K3: dual-softmax coeff + message scatter ----------------
__global__ __launch_bounds__(256) void k_edge2(const int* __restrict__ src,
                                               const int* __restrict__ dst) {
    int e = blockIdx.x * 256 + threadIdx.x;
    if (e >= N_EDGES) return;
    int s = src[e], d = dst[e];
    uint4 raw = *(const uint4*)(g_eexp + (size_t)e * 8);
    const __nv_bfloat162* pr = reinterpret_cast<const __nv_bfloat162*>(&raw);
    float2 e01 = __bfloat1622float2(pr[0]);
    float2 e23 = __bfloat1622float2(pr[1]);
    float2 e45 = __bfloat1622float2(pr[2]);
    float2 e67 = __bfloat1622float2(pr[3]);
    uint4 rsd = *(const uint4*)(g_sdh + (size_t)d * 8);   // 16B gather
    uint4 rfc = *(const uint4*)(g_fch + (size_t)s * 8);   // 16B gather
    float sd[8], fc[8];
    unpk8h(rsd, sd);
    unpk8h(rfc, fc);

    float m0 = e01.x * sd[0] * fc[0];
    float m1 = e01.y * sd[1] * fc[1];
    float m2 = e23.x * sd[2] * fc[2];
    float m3 = e23.y * sd[3] * fc[3];
    float m4 = e45.x * sd[4] * fc[4];
    float m5 = e45.y * sd[5] * fc[5];
    float m6 = e67.x * sd[6] * fc[6];
    float m7 = e67.y * sd[7] * fc[7];

    red4(g_msg + (size_t)d * 8,     m0, m1, m2, m3);
    red4(g_msg + (size_t)d * 8 + 4, m4, m5, m6, m7);
}

// ---------------- K4: BN statistics ----------------
__global__ __launch_bounds__(256) void k_stats() {
    int n = blockIdx.x * 256 + threadIdx.x;
    float a[8], q[8];
#pragma unroll
    for (int h = 0; h < 8; h++) { a[h] = 0.f; q[h] = 0.f; }
    if (n < N_NODES) {
        const float4* mp = (const float4*)(g_msg + (size_t)n * 8);
        float4 m0 = mp[0], m1 = mp[1];
        a[0] = m0.x; a[1] = m0.y; a[2] = m0.z; a[3] = m0.w;
        a[4] = m1.x; a[5] = m1.y; a[6] = m1.z; a[7] = m1.w;
#pragma unroll
        for (int h = 0; h < 8; h++) q[h] = a[h] * a[h];
    }
#pragma unroll
    for (int h = 0; h < 8; h++) {
        for (int off = 16; off; off >>= 1) {
            a[h] += __shfl_xor_sync(0xFFFFFFFFu, a[h], off);
            q[h] += __shfl_xor_sync(0xFFFFFFFFu, q[h], off);
        }
    }
    if ((threadIdx.x & 31) == 0) {
#pragma unroll
        for (int h = 0; h < 8; h++) {
            atomicAdd(&g_stats[h], a[h]);
            atomicAdd(&g_stats[8 + h], q[h]);
        }
    }
}

// ---------------- K5: fold BN + W_agg + b_apply_dst into W2 / b2 ----------------
__global__ void k_prep(const float* __restrict__ gamma, const float* __restrict__ beta,
                       const float* __restrict__ Wagg, const float* __restrict__ bagg,
                       const float* __restrict__ bapd) {
    __shared__ float sc[8], sh[8];
    int tid = threadIdx.x;
    if (tid < 8) {
        float mu  = g_stats[tid] * (1.f / N_NODES);
        float var = g_stats[8 + tid] * (1.f / N_NODES) - mu * mu;
        float s = gamma[tid] * rsqrtf(var + 1e-5f);
        sc[tid] = s;
        sh[tid] = beta[tid] - mu * s;
    }
    __syncthreads();
    int c = tid;
    float b = bagg[c] + bapd[c];
#pragma unroll
    for (int h = 0; h < 8; h++) {
        float w = Wagg[h * 256 + c];
        g_w2[h * 256 + c] = sc[h] * w;
        b += sh[h] * w;
    }
    g_b2[c] = b;
}

// ---------------- K6: fused double GEMM, single-fp16 operands, 64-row CTA, 2 CTAs/SM ----
#define IH    0         // A1 chunk (stride 144) / inter fp16 (stride 528, 33792) / epi2 stage part
#define BO    33792     // B single buffer 256*144 = 36864
#define W2O   70656     // w2 8*256*4 = 8192
#define MSO   78848     // msgs 64*8*4 = 2048
#define TC_SMEM 80896   // 2 CTAs/SM

__device__ __forceinline__ void gemm_chunk(float acc[2][8][4],
                                           uint32_t aB, uint32_t astride,
                                           uint32_t bB, int wm, int wn, int lane) {
    const uint32_t arow = (uint32_t)(wm * 32 + (lane & 15));
    const uint32_t akh  = (uint32_t)((lane >> 4) * 8);
    const uint32_t brow = (uint32_t)(wn * 64 + (lane & 7) + ((lane >> 4) & 1) * 8);
    const uint32_t bkh  = (uint32_t)(((lane >> 3) & 1) * 8);
#pragma unroll
    for (int ks = 0; ks < 64; ks += 16) {
        uint32_t a[2][4];
#pragma unroll
        for (int mi = 0; mi < 2; mi++) {
            uint32_t ao = (arow + mi * 16) * astride + (ks + akh) * 2;
            ldsm4(aB + ao, a[mi]);
        }
#pragma unroll
        for (int nip = 0; nip < 4; nip++) {
            uint32_t bo = (brow + nip * 16) * 144 + (ks + bkh) * 2;
            uint32_t b[4];
            ldsm4(bB + bo, b);
#pragma unroll
            for (int mi = 0; mi < 2; mi++) {
                mma16816(acc[mi][nip * 2],     a[mi], b[0], b[1]);
                mma16816(acc[mi][nip * 2 + 1], a[mi], b[2], b[3]);
            }
        }
    }
}

__global__ void __launch_bounds__(256, 2) k_tc(const float* __restrict__ bap,
                                               float* __restrict__ out) {
    extern __shared__ char sm[];
    const uint32_t sb = smem_u32(sm);
    const int tid = threadIdx.x;
    const int warp = tid >> 5, lane = tid & 31;
    const int wm = warp >> 2, wn = warp & 3;
    const int row0 = blockIdx.x * 64;

    float* w2s  = (float*)(sm + W2O);
    float* msgs = (float*)(sm + MSO);

    auto pfA = [&](int kc) {
#pragma unroll
        for (int i = tid; i < 512; i += 256) {
            int r = i >> 3, s = i & 7;
            int node = row0 + r; if (node >= N_NODES) node = N_NODES - 1;
            cpa16(sb + IH + (uint32_t)(r * 144 + s * 16),
                  g_fh + (size_t)node * 256 + kc + s * 8);
        }
    };
    auto pfB = [&](const __half* W, int kc) {
#pragma unroll
        for (int i = tid; i < 2048; i += 256) {
            int n = i >> 3, s = i & 7;
            cpa16(sb + BO + (uint32_t)(n * 144 + s * 16), W + (size_t)n * 256 + kc + s * 8);
        }
    };

    for (int i = tid; i < 2048; i += 256) w2s[i] = g_w2[i];
    for (int i = tid; i < 512; i += 256) {
        int r = i >> 3;
        int node = row0 + r; if (node >= N_NODES) node = N_NODES - 1;
        msgs[i] = g_msg[(size_t)node * 8 + (i & 7)];
    }

    float acc[2][8][4];
#pragma unroll
    for (int mi = 0; mi < 2; mi++)
#pragma unroll
        for (int ni = 0; ni < 8; ni++)
#pragma unroll
            for (int j = 0; j < 4; j++) acc[mi][ni][j] = 0.f;

    // ================= GEMM1: feat(fp16) @ WdT =================
#pragma unroll
    for (int ci = 0; ci < 4; ci++) {
        pfA(ci * 64);
        pfB(g_WdT, ci * 64);
        CP_COMMIT();
        CP_WAIT(0);
        __syncthreads();
        gemm_chunk(acc, sb + IH, 144, sb + BO, wm, wn, lane);
        __syncthreads();
    }

    // ====== epilogue1: + bias + msg@W2, leaky, fp16 round -> inter (stride 528B) ======
    {
        const int g = lane >> 2, t = lane & 3;
#pragma unroll
        for (int mi = 0; mi < 2; mi++) {
            const int rA = wm * 32 + mi * 16 + g, rB = rA + 8;
            float mA[8], mB[8];
#pragma unroll
            for (int h = 0; h < 8; h++) { mA[h] = msgs[rA * 8 + h]; mB[h] = msgs[rB * 8 + h]; }
#pragma unroll
            for (int ni = 0; ni < 8; ni++) {
                const int c0 = wn * 64 + ni * 8 + 2 * t, c1 = c0 + 1;
                float b0 = g_b2[c0], b1 = g_b2[c1];
                float vA0 = acc[mi][ni][0] + b0;
                float vA1 = acc[mi][ni][1] + b1;
                float vB0 = acc[mi][ni][2] + b0;
                float vB1 = acc[mi][ni][3] + b1;
#pragma unroll
                for (int h = 0; h < 8; h++) {
                    float w0 = w2s[h * 256 + c0], w1 = w2s[h * 256 + c1];
                    vA0 += mA[h] * w0; vA1 += mA[h] * w1;
                    vB0 += mB[h] * w0; vB1 += mB[h] * w1;
                }
                *(uint32_t*)(sm + IH + rA * 528 + c0 * 2) = pack2h(leaky(vA0), leaky(vA1));
                *(uint32_t*)(sm + IH + rB * 528 + c0 * 2) = pack2h(leaky(vB0), leaky(vB1));
                acc[mi][ni][0] = 0.f; acc[mi][ni][1] = 0.f;
                acc[mi][ni][2] = 0.f; acc[mi][ni][3] = 0.f;
            }
        }
    }

    // ================= GEMM2: inter(fp16) @ WaT =================
#pragma unroll
    for (int ci = 0; ci < 4; ci++) {
        pfB(g_WaT, ci * 64);
        CP_COMMIT();
        CP_WAIT(0);
        __syncthreads();
        gemm_chunk(acc, sb + IH + ci * 128, 528, sb + BO, wm, wn, lane);
        __syncthreads();
    }

    // ====== epilogue2: + ba -> stage (fp32, stride 264 floats) -> coalesced store ======
    {
        float* stage = (float*)(sm + IH);
        const int g = lane >> 2, t = lane & 3;
#pragma unroll
        for (int mi = 0; mi < 2; mi++) {
            const int rA = wm * 32 + mi * 16 + g, rB = rA + 8;
#pragma unroll
            for (int ni = 0; ni < 8; ni++) {
                const int c0 = wn * 64 + ni * 8 + 2 * t;
                float b0 = bap[c0], b1 = bap[c0 + 1];
                *(float2*)(stage + rA * 264 + c0) = make_float2(acc[mi][ni][0] + b0, acc[mi][ni][1] + b1);
                *(float2*)(stage + rB * 264 + c0) = make_float2(acc[mi][ni][2] + b0, acc[mi][ni][3] + b1);
            }
        }
        __syncthreads();
        for (int idx = tid; idx < 64 * 64; idx += 256) {
            int r = idx >> 6, c4 = (idx & 63) << 2;
            int node = row0 + r;
            if (node < N_NODES)
                *(float4*)(out + (size_t)node * 256 + c4) = *(const float4*)(stage + r * 264 + c4);
        }
    }
}

// ---------------- launch ----------------
extern "C" void kernel_launch(void* const* d_in, const int* in_sizes, int n_in,
                              void* d_out, int out_size) {
    const float* feat  = (const float*)d_in[0];
    const float* fedge = (const float*)d_in[1];
    const int*   src   = (const int*)d_in[2];
    const int*   dst   = (const int*)d_in[3];
    const float* Wp    = (const float*)d_in[4];
    const float* Was   = (const float*)d_in[5];
    const float* Wad   = (const float*)d_in[6];
    const float* Wae   = (const float*)d_in[7];
    const float* gamma = (const float*)d_in[8];
    const float* beta  = (const float*)d_in[9];
    const float* Wagg  = (const float*)d_in[10];
    const float* bagg  = (const float*)d_in[11];
    const float* Wapd  = (const float*)d_in[12];
    const float* bapd  = (const float*)d_in[13];
    const float* Wap   = (const float*)d_in[14];
    const float* bap   = (const float*)d_in[15];
    float* out = (float*)d_out;

    k_node<<<N_NODES / 32, 256>>>(feat, Wp, Was, Wad);
    k_split<<<dim3(8, 8, 2), dim3(32, 8)>>>(Wapd, Wap);
    k_edge1<<<(N_EDGES + 255) / 256, 256>>>(fedge, src, dst, Wae);
    k_rs<<<(N_NODES * N_HEAD + 255) / 256, 256>>>();
    k_edge2<<<(N_EDGES + 255) / 256, 256>>>(src, dst);
    k_stats<<<(N_NODES + 255) / 256, 256>>>();
    k_prep<<<1, 256>>>(gamma, beta, Wagg, bagg, bapd);

    cudaFuncSetAttribute(k_tc, cudaFuncAttributeMaxDynamicSharedMemorySize, TC_SMEM);
    k_tc<<<N_TILES, 256, TC_SMEM>>>(bap, out);
}